// round 2
// baseline (speedup 1.0000x reference)
#include <cuda_runtime.h>
#include <math.h>

#define B_ 32768
#define F_ 512
#define H_ 256
#define C_ 100
#define E_ 8

// Scratch (static device globals — no allocations allowed)
__device__ float g_h[(size_t)E_ * B_ * H_];        // 256 MB: relu(x@W1+b1) per expert
__device__ float g_preds[(size_t)E_ * B_ * C_];    // fallback preds if out buffer is combined-only
__device__ int   g_top2[B_];
__device__ int   g_counts[E_];

// ---------------------------------------------------------------------------
// Gating: logits = x @ Wg ; top-2 (softmax monotonic -> same indices)
// One warp per row. Wg (512x8) staged in smem with stride-9 padding.
// ---------------------------------------------------------------------------
__global__ __launch_bounds__(256) void gate_kernel(const float* __restrict__ x,
                                                   const float* __restrict__ Wg) {
    __shared__ float wgs[F_ * 9];
    __shared__ int cnt[E_];
    const int tid = threadIdx.x;
    if (tid < E_) cnt[tid] = 0;
    for (int i = tid; i < F_ * E_; i += 256) {
        int f = i >> 3, e = i & 7;
        wgs[f * 9 + e] = Wg[i];
    }
    __syncthreads();

    const int warp = tid >> 5, lane = tid & 31;
    const int row = blockIdx.x * 8 + warp;
    const float* xr = x + (size_t)row * F_;

    float acc[E_];
#pragma unroll
    for (int e = 0; e < E_; e++) acc[e] = 0.f;
#pragma unroll
    for (int i = 0; i < F_ / 32; i++) {
        int f = i * 32 + lane;
        float xv = xr[f];
#pragma unroll
        for (int e = 0; e < E_; e++) acc[e] += xv * wgs[f * 9 + e];
    }
#pragma unroll
    for (int off = 16; off; off >>= 1)
#pragma unroll
        for (int e = 0; e < E_; e++)
            acc[e] += __shfl_xor_sync(0xffffffffu, acc[e], off);

    if (lane == 0) {
        int i1 = 0;
#pragma unroll
        for (int e = 1; e < E_; e++) if (acc[e] > acc[i1]) i1 = e;   // strict > : earliest index on tie
        int i2 = (i1 == 0) ? 1 : 0;
#pragma unroll
        for (int e = 0; e < E_; e++) if (e != i1 && acc[e] > acc[i2]) i2 = e;
        g_top2[row] = i1 | (i2 << 8);
        atomicAdd(&cnt[i1], 1);
        atomicAdd(&cnt[i2], 1);
    }
    __syncthreads();
    if (tid < E_ && cnt[tid]) atomicAdd(&g_counts[tid], cnt[tid]);
}

// ---------------------------------------------------------------------------
// GEMM1: g_h[e] = relu(x[B,F] @ W1[e][F,H] + b1[e])
// 128x128x16 tile, 256 threads, 8x8 microtile, double-buffered smem.
// Grid: (H/128, B/128, E)
// ---------------------------------------------------------------------------
__global__ __launch_bounds__(256, 2)
void gemm1_kernel(const float* __restrict__ X, const float* __restrict__ W1,
                  const float* __restrict__ b1) {
    __shared__ float As[2][16][128];   // As[k][m]
    __shared__ float Bs[2][16][128];   // Bs[k][n]

    const int e  = blockIdx.z;
    const int n0 = blockIdx.x * 128;
    const int m0 = blockIdx.y * 128;
    const float* Bsrc = W1 + (size_t)e * (F_ * H_);
    const int tid = threadIdx.x;

    // A loader: thread -> row m = tid>>1, 8 consecutive k at (tid&1)*8
    const int a_m = tid >> 1;
    const int a_k = (tid & 1) * 8;
    const float* aPtr = X + (size_t)(m0 + a_m) * F_ + a_k;
    // B loader: thread -> k row tid>>4, 8 consecutive n at (tid&15)*8
    const int b_k = tid >> 4;
    const int b_n = (tid & 15) * 8;
    const float* bPtr = Bsrc + (size_t)b_k * H_ + n0 + b_n;

    float4 aR0, aR1, bR0, bR1;
    aR0 = *(const float4*)(aPtr);
    aR1 = *(const float4*)(aPtr + 4);
    bR0 = *(const float4*)(bPtr);
    bR1 = *(const float4*)(bPtr + 4);
    As[0][a_k + 0][a_m] = aR0.x; As[0][a_k + 1][a_m] = aR0.y;
    As[0][a_k + 2][a_m] = aR0.z; As[0][a_k + 3][a_m] = aR0.w;
    As[0][a_k + 4][a_m] = aR1.x; As[0][a_k + 5][a_m] = aR1.y;
    As[0][a_k + 6][a_m] = aR1.z; As[0][a_k + 7][a_m] = aR1.w;
    *(float4*)&Bs[0][b_k][b_n]     = bR0;
    *(float4*)&Bs[0][b_k][b_n + 4] = bR1;
    __syncthreads();

    const int tx = (tid & 15) * 8;   // n offset
    const int ty = (tid >> 4) * 8;   // m offset
    float acc[8][8];
#pragma unroll
    for (int i = 0; i < 8; i++)
#pragma unroll
        for (int j = 0; j < 8; j++) acc[i][j] = 0.f;

    const int NT = F_ / 16;  // 32
    for (int t = 0; t < NT; t++) {
        const int buf = t & 1;
        if (t + 1 < NT) {
            const float* ap = aPtr + (t + 1) * 16;
            aR0 = *(const float4*)(ap);
            aR1 = *(const float4*)(ap + 4);
            const float* bp = bPtr + (size_t)(t + 1) * 16 * H_;
            bR0 = *(const float4*)(bp);
            bR1 = *(const float4*)(bp + 4);
        }
#pragma unroll
        for (int k = 0; k < 16; k++) {
            float4 a0 = *(const float4*)&As[buf][k][ty];
            float4 a1 = *(const float4*)&As[buf][k][ty + 4];
            float4 b0 = *(const float4*)&Bs[buf][k][tx];
            float4 b1 = *(const float4*)&Bs[buf][k][tx + 4];
            float av[8] = {a0.x, a0.y, a0.z, a0.w, a1.x, a1.y, a1.z, a1.w};
            float bv[8] = {b0.x, b0.y, b0.z, b0.w, b1.x, b1.y, b1.z, b1.w};
#pragma unroll
            for (int i = 0; i < 8; i++)
#pragma unroll
                for (int j = 0; j < 8; j++) acc[i][j] += av[i] * bv[j];
        }
        if (t + 1 < NT) {
            const int nb = buf ^ 1;
            As[nb][a_k + 0][a_m] = aR0.x; As[nb][a_k + 1][a_m] = aR0.y;
            As[nb][a_k + 2][a_m] = aR0.z; As[nb][a_k + 3][a_m] = aR0.w;
            As[nb][a_k + 4][a_m] = aR1.x; As[nb][a_k + 5][a_m] = aR1.y;
            As[nb][a_k + 6][a_m] = aR1.z; As[nb][a_k + 7][a_m] = aR1.w;
            *(float4*)&Bs[nb][b_k][b_n]     = bR0;
            *(float4*)&Bs[nb][b_k][b_n + 4] = bR1;
            __syncthreads();
        }
    }

    // epilogue: + bias, relu, store to g_h
    float bias[8];
    *(float4*)&bias[0] = *(const float4*)(b1 + e * H_ + n0 + tx);
    *(float4*)&bias[4] = *(const float4*)(b1 + e * H_ + n0 + tx + 4);
    float* outp = g_h + ((size_t)e * B_ + m0 + ty) * H_ + n0 + tx;
#pragma unroll
    for (int i = 0; i < 8; i++) {
        float4 o0, o1;
        o0.x = fmaxf(acc[i][0] + bias[0], 0.f);
        o0.y = fmaxf(acc[i][1] + bias[1], 0.f);
        o0.z = fmaxf(acc[i][2] + bias[2], 0.f);
        o0.w = fmaxf(acc[i][3] + bias[3], 0.f);
        o1.x = fmaxf(acc[i][4] + bias[4], 0.f);
        o1.y = fmaxf(acc[i][5] + bias[5], 0.f);
        o1.z = fmaxf(acc[i][6] + bias[6], 0.f);
        o1.w = fmaxf(acc[i][7] + bias[7], 0.f);
        *(float4*)(outp + (size_t)i * H_)     = o0;
        *(float4*)(outp + (size_t)i * H_ + 4) = o1;
    }
}

// ---------------------------------------------------------------------------
// GEMM2: preds[e] = g_h[e][B,H] @ W2[e][H,C] + b2[e]
// Block: 128 rows x all 100 cols (padded to 112). Thread: 8 rows x 7 cols.
// Grid: (B/128, E)
// ---------------------------------------------------------------------------
__global__ __launch_bounds__(256)
void gemm2_kernel(const float* __restrict__ W2, const float* __restrict__ b2,
                  float* __restrict__ preds_arg) {
    __shared__ float As[16][128];   // As[k][m]
    __shared__ float Bs[16][112];   // Bs[k][c]

    float* preds = preds_arg ? preds_arg : g_preds;
    const int e  = blockIdx.y;
    const int m0 = blockIdx.x * 128;
    const float* Asrc = g_h + (size_t)e * B_ * H_;
    const float* Bsrc = W2 + (size_t)e * H_ * C_;
    const int tid = threadIdx.x;

    const int a_m = tid >> 1;
    const int a_k = (tid & 1) * 8;
    const float* aPtr = Asrc + (size_t)(m0 + a_m) * H_ + a_k;

    const int tx = (tid & 15) * 7;   // col offset (0..105)
    const int ty = (tid >> 4) * 8;   // row offset
    float acc[8][7];
#pragma unroll
    for (int i = 0; i < 8; i++)
#pragma unroll
        for (int j = 0; j < 7; j++) acc[i][j] = 0.f;

    for (int t = 0; t < H_ / 16; t++) {
        float4 aR0 = *(const float4*)(aPtr + t * 16);
        float4 aR1 = *(const float4*)(aPtr + t * 16 + 4);
        As[a_k + 0][a_m] = aR0.x; As[a_k + 1][a_m] = aR0.y;
        As[a_k + 2][a_m] = aR0.z; As[a_k + 3][a_m] = aR0.w;
        As[a_k + 4][a_m] = aR1.x; As[a_k + 5][a_m] = aR1.y;
        As[a_k + 6][a_m] = aR1.z; As[a_k + 7][a_m] = aR1.w;
        for (int i = tid; i < 16 * C_; i += 256) {
            int kk = i / C_, cc = i - kk * C_;
            Bs[kk][cc] = Bsrc[(size_t)(t * 16 + kk) * C_ + cc];
        }
        __syncthreads();
#pragma unroll
        for (int k = 0; k < 16; k++) {
            float4 a0 = *(const float4*)&As[k][ty];
            float4 a1 = *(const float4*)&As[k][ty + 4];
            float av[8] = {a0.x, a0.y, a0.z, a0.w, a1.x, a1.y, a1.z, a1.w};
            float bv[7];
#pragma unroll
            for (int j = 0; j < 7; j++) bv[j] = Bs[k][tx + j];
#pragma unroll
            for (int i = 0; i < 8; i++)
#pragma unroll
                for (int j = 0; j < 7; j++) acc[i][j] += av[i] * bv[j];
        }
        __syncthreads();
    }

#pragma unroll
    for (int j = 0; j < 7; j++) {
        int c = tx + j;
        if (c < C_) {
            float bias = b2[e * C_ + c];
#pragma unroll
            for (int i = 0; i < 8; i++)
                preds[((size_t)e * B_ + m0 + ty + i) * C_ + c] = acc[i][j] + bias;
        }
    }
}

// ---------------------------------------------------------------------------
// Combine: combined[b] = 0.5*(softmax(preds[e1,b]) + softmax(preds[e2,b]))
// One warp per row; lane handles cols {lane, lane+32, lane+64, lane+96}.
// ---------------------------------------------------------------------------
__global__ __launch_bounds__(256)
void combine_kernel(const float* __restrict__ preds_arg, float* __restrict__ combined) {
    const float* preds = preds_arg ? preds_arg : g_preds;
    const int warp = threadIdx.x >> 5, lane = threadIdx.x & 31;
    const int row = blockIdx.x * 8 + warp;
    const int packed = g_top2[row];
    const int e1 = packed & 0xFF, e2 = (packed >> 8) & 0xFF;
    const float* p1 = preds + ((size_t)e1 * B_ + row) * C_;
    const float* p2 = preds + ((size_t)e2 * B_ + row) * C_;

    float v1[4], v2[4];
#pragma unroll
    for (int i = 0; i < 4; i++) {
        int c = lane + i * 32;
        bool ok = c < C_;
        v1[i] = ok ? p1[c] : -3.4e38f;
        v2[i] = ok ? p2[c] : -3.4e38f;
    }
    float m1 = fmaxf(fmaxf(v1[0], v1[1]), fmaxf(v1[2], v1[3]));
    float m2 = fmaxf(fmaxf(v2[0], v2[1]), fmaxf(v2[2], v2[3]));
#pragma unroll
    for (int off = 16; off; off >>= 1) {
        m1 = fmaxf(m1, __shfl_xor_sync(0xffffffffu, m1, off));
        m2 = fmaxf(m2, __shfl_xor_sync(0xffffffffu, m2, off));
    }
    float s1 = 0.f, s2 = 0.f;
#pragma unroll
    for (int i = 0; i < 4; i++) {
        int c = lane + i * 32;
        v1[i] = (c < C_) ? expf(v1[i] - m1) : 0.f;
        v2[i] = (c < C_) ? expf(v2[i] - m2) : 0.f;
        s1 += v1[i];
        s2 += v2[i];
    }
#pragma unroll
    for (int off = 16; off; off >>= 1) {
        s1 += __shfl_xor_sync(0xffffffffu, s1, off);
        s2 += __shfl_xor_sync(0xffffffffu, s2, off);
    }
    const float r1 = 0.5f / s1, r2 = 0.5f / s2;
    float* outr = combined + (size_t)row * C_;
#pragma unroll
    for (int i = 0; i < 4; i++) {
        int c = lane + i * 32;
        if (c < C_) outr[c] = v1[i] * r1 + v2[i] * r2;
    }
}

__global__ void zero_counts_kernel() {
    if (threadIdx.x < E_) g_counts[threadIdx.x] = 0;
}
__global__ void write_counts_kernel(float* __restrict__ dst) {
    if (threadIdx.x < E_) dst[threadIdx.x] = (float)g_counts[threadIdx.x];
}

// ---------------------------------------------------------------------------
extern "C" void kernel_launch(void* const* d_in, const int* in_sizes, int n_in,
                              void* d_out, int out_size) {
    const float* x  = (const float*)d_in[0];
    const float* W1 = (const float*)d_in[1];
    const float* b1 = (const float*)d_in[2];
    const float* W2 = (const float*)d_in[3];
    const float* b2 = (const float*)d_in[4];
    const float* Wg = (const float*)d_in[5];
    float* out = (float*)d_out;

    const size_t n_combined = (size_t)B_ * C_;            // 3,276,800
    const size_t n_preds    = (size_t)E_ * B_ * C_;       // 26,214,400
    const bool has_preds  = (size_t)out_size >= n_combined + n_preds;
    const bool has_counts = (size_t)out_size >= n_combined + n_preds + E_;

    float* combined  = out;
    float* preds_out = has_preds ? out + n_combined : nullptr;  // nullptr -> g_preds fallback

    zero_counts_kernel<<<1, 32>>>();
    gate_kernel<<<B_ / 8, 256>>>(x, Wg);

    dim3 g1(H_ / 128, B_ / 128, E_);
    gemm1_kernel<<<g1, 256>>>(x, W1, b1);

    dim3 g2(B_ / 128, E_);
    gemm2_kernel<<<g2, 256>>>(W2, b2, preds_out);

    combine_kernel<<<B_ / 8, 256>>>(preds_out, combined);

    if (has_counts) write_counts_kernel<<<1, 32>>>(out + n_combined + n_preds);
}

// round 4
// speedup vs baseline: 2.5095x; 2.5095x over previous
#include <cuda_runtime.h>
#include <cuda_bf16.h>
#include <cstdint>
#include <math.h>

#define B_ 32768
#define F_ 512
#define H_ 256
#define C_ 100
#define E_ 8

// ---------------- device-global scratch (no allocs allowed) ----------------
__device__ __align__(128) __nv_bfloat16 g_xHi[(size_t)B_ * F_];
__device__ __align__(128) __nv_bfloat16 g_xLo[(size_t)B_ * F_];
__device__ __align__(128) __nv_bfloat16 g_w1tHi[(size_t)E_ * H_ * F_];   // [e][h][f]
__device__ __align__(128) __nv_bfloat16 g_w1tLo[(size_t)E_ * H_ * F_];
__device__ __align__(128) __nv_bfloat16 g_w2tHi[(size_t)E_ * 128 * H_]; // [e][c pad128][h]
__device__ __align__(128) __nv_bfloat16 g_w2tLo[(size_t)E_ * 128 * H_];
__device__ __align__(128) __nv_bfloat16 g_hHi[(size_t)E_ * B_ * H_];
__device__ __align__(128) __nv_bfloat16 g_hLo[(size_t)E_ * B_ * H_];
__device__ float g_preds[(size_t)E_ * B_ * C_];
__device__ int   g_top2[B_];
__device__ int   g_counts[E_];

// ---------------- helpers ----------------
__device__ __forceinline__ uint32_t s2u(const void* p) {
    uint32_t a;
    asm("{ .reg .u64 t; cvta.to.shared.u64 t, %1; cvt.u32.u64 %0, t; }" : "=r"(a) : "l"(p));
    return a;
}
__device__ __forceinline__ uint32_t pack2(float f0, float f1, uint32_t& lo) {
    __nv_bfloat16 h0 = __float2bfloat16(f0), h1 = __float2bfloat16(f1);
    __nv_bfloat16 l0 = __float2bfloat16(f0 - __bfloat162float(h0));
    __nv_bfloat16 l1 = __float2bfloat16(f1 - __bfloat162float(h1));
    lo = (uint32_t)__bfloat16_as_ushort(l0) | ((uint32_t)__bfloat16_as_ushort(l1) << 16);
    return (uint32_t)__bfloat16_as_ushort(h0) | ((uint32_t)__bfloat16_as_ushort(h1) << 16);
}
__device__ __forceinline__ void ldm4(uint32_t* r, uint32_t a) {
    asm volatile("ldmatrix.sync.aligned.m8n8.x4.shared.b16 {%0,%1,%2,%3}, [%4];"
                 : "=r"(r[0]), "=r"(r[1]), "=r"(r[2]), "=r"(r[3]) : "r"(a));
}
__device__ __forceinline__ void mma16816(float* c, const uint32_t* a, const uint32_t* b) {
    asm volatile("mma.sync.aligned.m16n8k16.row.col.f32.bf16.bf16.f32 "
                 "{%0,%1,%2,%3}, {%4,%5,%6,%7}, {%8,%9}, {%0,%1,%2,%3};"
                 : "+f"(c[0]), "+f"(c[1]), "+f"(c[2]), "+f"(c[3])
                 : "r"(a[0]), "r"(a[1]), "r"(a[2]), "r"(a[3]), "r"(b[0]), "r"(b[1]));
}
__device__ __forceinline__ void cpa(uint32_t dst, const void* src) {
    asm volatile("cp.async.cg.shared.global [%0], [%1], 16;" :: "r"(dst), "l"(src));
}

// ---------------- prep: fp32 -> bf16 hi/lo split ----------------
__global__ __launch_bounds__(256) void split_x(const float* __restrict__ x) {
    size_t gid = (size_t)blockIdx.x * 256 + threadIdx.x;      // B*F/8 threads
    const float4* s = (const float4*)(x + gid * 8);
    float4 f0 = s[0], f1 = s[1];
    uint4 hi, lo;
    hi.x = pack2(f0.x, f0.y, lo.x); hi.y = pack2(f0.z, f0.w, lo.y);
    hi.z = pack2(f1.x, f1.y, lo.z); hi.w = pack2(f1.z, f1.w, lo.w);
    *(uint4*)(g_xHi + gid * 8) = hi;
    *(uint4*)(g_xLo + gid * 8) = lo;
}
__global__ __launch_bounds__(256) void split_w1(const float* __restrict__ W1) {
    int gid = blockIdx.x * 256 + threadIdx.x;                 // 8*256*64
    int e = gid >> 14, h = (gid >> 6) & 255, f8 = gid & 63;
    float f[8];
#pragma unroll
    for (int j = 0; j < 8; j++) f[j] = W1[((size_t)e * F_ + f8 * 8 + j) * H_ + h];
    uint4 hi, lo;
    hi.x = pack2(f[0], f[1], lo.x); hi.y = pack2(f[2], f[3], lo.y);
    hi.z = pack2(f[4], f[5], lo.z); hi.w = pack2(f[6], f[7], lo.w);
    size_t o = ((size_t)e * H_ + h) * F_ + f8 * 8;
    *(uint4*)(g_w1tHi + o) = hi;
    *(uint4*)(g_w1tLo + o) = lo;
}
__global__ __launch_bounds__(256) void split_w2(const float* __restrict__ W2) {
    int gid = blockIdx.x * 256 + threadIdx.x;                 // 8*128*32
    int e = gid >> 12, c = (gid >> 5) & 127, h8 = gid & 31;
    float f[8];
#pragma unroll
    for (int j = 0; j < 8; j++)
        f[j] = (c < C_) ? W2[((size_t)e * H_ + h8 * 8 + j) * C_ + c] : 0.f;
    uint4 hi, lo;
    hi.x = pack2(f[0], f[1], lo.x); hi.y = pack2(f[2], f[3], lo.y);
    hi.z = pack2(f[4], f[5], lo.z); hi.w = pack2(f[6], f[7], lo.w);
    size_t o = ((size_t)e * 128 + c) * H_ + h8 * 8;
    *(uint4*)(g_w2tHi + o) = hi;
    *(uint4*)(g_w2tLo + o) = lo;
}

// ---------------- HMMA GEMM, 3-term bf16 split ----------------
// MODE 0: h = relu(x @ W1^T + b1) -> g_hHi/g_hLo      (KT=512, NB=256)
// MODE 1: preds = h @ W2^T + b2 -> preds (n<100)      (KT=256, NB=128)
// CTA tile 128x128, 8 warps (4M x 2N), warp tile m32n64, Kstage=32.
#define STRB 80            // smem row stride bytes (40 bf16)
#define ARR 10240          // one [128][40] bf16 array
#define BUFB 40960         // 4 arrays per buffer
template <int KT, int MODE>
__global__ void __launch_bounds__(256)
mma_gemm(const float* __restrict__ bias, float* __restrict__ preds_arg) {
    extern __shared__ __align__(128) unsigned char sm[];
    const uint32_t sb = s2u(sm);
    const int tid = threadIdx.x, e = blockIdx.z;
    const int n0 = blockIdx.x * 128, m0 = blockIdx.y * 128;

    const __nv_bfloat16 *Ah, *Al, *Bh, *Bl;
    if (MODE == 0) {
        Ah = g_xHi; Al = g_xLo;
        Bh = g_w1tHi + (size_t)e * H_ * F_;
        Bl = g_w1tLo + (size_t)e * H_ * F_;
    } else {
        Ah = g_hHi + (size_t)e * B_ * H_;
        Al = g_hLo + (size_t)e * B_ * H_;
        Bh = g_w2tHi + (size_t)e * 128 * H_;
        Bl = g_w2tLo + (size_t)e * 128 * H_;
    }

    auto load_stage = [&](int buf, int k0) {
#pragma unroll
        for (int j = 0; j < 2; j++) {
            int idx = tid + j * 256;
            int r = idx >> 2, kc = (idx & 3) * 8;
            uint32_t d = sb + buf * BUFB + r * STRB + kc * 2;
            cpa(d,            Ah + (size_t)(m0 + r) * KT + k0 + kc);
            cpa(d + ARR,      Al + (size_t)(m0 + r) * KT + k0 + kc);
            cpa(d + 2 * ARR,  Bh + (size_t)(n0 + r) * KT + k0 + kc);
            cpa(d + 3 * ARR,  Bl + (size_t)(n0 + r) * KT + k0 + kc);
        }
        asm volatile("cp.async.commit_group;" ::: "memory");
    };

    const int l = tid & 31, warp = tid >> 5, wr = warp & 3, wc = warp >> 2;
    // A lane addr: row = wr*32 + mi*16 + l%16 ; colB = (l/16)*16 + h*32
    const uint32_t aOff = (uint32_t)(wr * 32 + (l & 15)) * STRB + (l >> 4) * 16;
    // B lane addr: n = wc*64 + ni*16 + (l/16)*8 + l%8 ; colB = ((l/8)&1)*16 + h*32
    const uint32_t bOff = (uint32_t)(wc * 64 + ((l >> 4) << 3) + (l & 7)) * STRB + ((l >> 3) & 1) * 16;

    float acc[2][8][4];
#pragma unroll
    for (int i = 0; i < 2; i++)
#pragma unroll
        for (int j = 0; j < 8; j++)
#pragma unroll
            for (int q = 0; q < 4; q++) acc[i][j][q] = 0.f;

    load_stage(0, 0);
    const int NS = KT / 32;
    for (int s = 0; s < NS; s++) {
        const int buf = s & 1;
        if (s + 1 < NS) {
            load_stage(buf ^ 1, (s + 1) * 32);
            asm volatile("cp.async.wait_group 1;" ::: "memory");
        } else {
            asm volatile("cp.async.wait_group 0;" ::: "memory");
        }
        __syncthreads();
        const uint32_t base = sb + buf * BUFB;
#pragma unroll
        for (int h = 0; h < 2; h++) {
            uint32_t ah[2][4], al[2][4];
            ldm4(ah[0], base + aOff + h * 32);
            ldm4(ah[1], base + aOff + 16 * STRB + h * 32);
            ldm4(al[0], base + ARR + aOff + h * 32);
            ldm4(al[1], base + ARR + aOff + 16 * STRB + h * 32);
#pragma unroll
            for (int ni = 0; ni < 4; ni++) {
                uint32_t bh4[4], bl4[4];
                ldm4(bh4, base + 2 * ARR + bOff + ni * 16 * STRB + h * 32);
                ldm4(bl4, base + 3 * ARR + bOff + ni * 16 * STRB + h * 32);
#pragma unroll
                for (int mi = 0; mi < 2; mi++)
#pragma unroll
                    for (int sj = 0; sj < 2; sj++) {
                        float* c = acc[mi][ni * 2 + sj];
                        mma16816(c, ah[mi], bh4 + 2 * sj);
                        mma16816(c, ah[mi], bl4 + 2 * sj);
                        mma16816(c, al[mi], bh4 + 2 * sj);
                    }
            }
        }
        __syncthreads();
    }

    // epilogue: acc frag c0,c1 -> (row=l/4, col=(l%4)*2 +0/1), c2,c3 -> row+8
    float* preds = preds_arg ? preds_arg : g_preds;
    const float* bsrc = bias + e * (MODE == 0 ? H_ : C_);
#pragma unroll
    for (int mi = 0; mi < 2; mi++) {
        int mB = m0 + wr * 32 + mi * 16 + (l >> 2);
#pragma unroll
        for (int ni = 0; ni < 8; ni++) {
            int n = n0 + wc * 64 + ni * 8 + (l & 3) * 2;
#pragma unroll
            for (int hf = 0; hf < 2; hf++) {
                int m = mB + hf * 8;
                float v0 = acc[mi][ni][hf * 2 + 0];
                float v1 = acc[mi][ni][hf * 2 + 1];
                if (MODE == 0) {
                    v0 = fmaxf(v0 + bsrc[n], 0.f);
                    v1 = fmaxf(v1 + bsrc[n + 1], 0.f);
                    uint32_t lo, hi = pack2(v0, v1, lo);
                    size_t o = ((size_t)e * B_ + m) * H_ + n;
                    *(uint32_t*)(g_hHi + o) = hi;
                    *(uint32_t*)(g_hLo + o) = lo;
                } else {
                    size_t o = ((size_t)e * B_ + m) * C_;
                    if (n < C_)     preds[o + n]     = v0 + bsrc[n];
                    if (n + 1 < C_) preds[o + n + 1] = v1 + bsrc[n + 1];
                }
            }
        }
    }
}

// ---------------- gating ----------------
__global__ __launch_bounds__(256) void gate_kernel(const float* __restrict__ x,
                                                   const float* __restrict__ Wg) {
    __shared__ float wgs[F_ * 9];
    __shared__ int cnt[E_];
    const int tid = threadIdx.x;
    if (tid < E_) cnt[tid] = 0;
    for (int i = tid; i < F_ * E_; i += 256) {
        int f = i >> 3, e = i & 7;
        wgs[f * 9 + e] = Wg[i];
    }
    __syncthreads();
    const int warp = tid >> 5, lane = tid & 31;
    const int row = blockIdx.x * 8 + warp;
    const float* xr = x + (size_t)row * F_;
    float acc[E_];
#pragma unroll
    for (int e = 0; e < E_; e++) acc[e] = 0.f;
#pragma unroll
    for (int i = 0; i < F_ / 32; i++) {
        int f = i * 32 + lane;
        float xv = xr[f];
#pragma unroll
        for (int e = 0; e < E_; e++) acc[e] += xv * wgs[f * 9 + e];
    }
#pragma unroll
    for (int off = 16; off; off >>= 1)
#pragma unroll
        for (int e = 0; e < E_; e++) acc[e] += __shfl_xor_sync(0xffffffffu, acc[e], off);
    if (lane == 0) {
        int i1 = 0;
#pragma unroll
        for (int e = 1; e < E_; e++) if (acc[e] > acc[i1]) i1 = e;
        int i2 = (i1 == 0) ? 1 : 0;
#pragma unroll
        for (int e = 0; e < E_; e++) if (e != i1 && acc[e] > acc[i2]) i2 = e;
        g_top2[row] = i1 | (i2 << 8);
        atomicAdd(&cnt[i1], 1);
        atomicAdd(&cnt[i2], 1);
    }
    __syncthreads();
    if (tid < E_ && cnt[tid]) atomicAdd(&g_counts[tid], cnt[tid]);
}

// ---------------- combine ----------------
__global__ __launch_bounds__(256)
void combine_kernel(const float* __restrict__ preds_arg, float* __restrict__ combined) {
    const float* preds = preds_arg ? preds_arg : g_preds;
    const int warp = threadIdx.x >> 5, lane = threadIdx.x & 31;
    const int row = blockIdx.x * 8 + warp;
    const int packed = g_top2[row];
    const int e1 = packed & 0xFF, e2 = (packed >> 8) & 0xFF;
    const float* p1 = preds + ((size_t)e1 * B_ + row) * C_;
    const float* p2 = preds + ((size_t)e2 * B_ + row) * C_;
    float v1[4], v2[4];
#pragma unroll
    for (int i = 0; i < 4; i++) {
        int c = lane + i * 32;
        bool ok = c < C_;
        v1[i] = ok ? p1[c] : -3.4e38f;
        v2[i] = ok ? p2[c] : -3.4e38f;
    }
    float m1 = fmaxf(fmaxf(v1[0], v1[1]), fmaxf(v1[2], v1[3]));
    float m2 = fmaxf(fmaxf(v2[0], v2[1]), fmaxf(v2[2], v2[3]));
#pragma unroll
    for (int off = 16; off; off >>= 1) {
        m1 = fmaxf(m1, __shfl_xor_sync(0xffffffffu, m1, off));
        m2 = fmaxf(m2, __shfl_xor_sync(0xffffffffu, m2, off));
    }
    float s1 = 0.f, s2 = 0.f;
#pragma unroll
    for (int i = 0; i < 4; i++) {
        int c = lane + i * 32;
        v1[i] = (c < C_) ? expf(v1[i] - m1) : 0.f;
        v2[i] = (c < C_) ? expf(v2[i] - m2) : 0.f;
        s1 += v1[i]; s2 += v2[i];
    }
#pragma unroll
    for (int off = 16; off; off >>= 1) {
        s1 += __shfl_xor_sync(0xffffffffu, s1, off);
        s2 += __shfl_xor_sync(0xffffffffu, s2, off);
    }
    const float r1 = 0.5f / s1, r2 = 0.5f / s2;
    float* outr = combined + (size_t)row * C_;
#pragma unroll
    for (int i = 0; i < 4; i++) {
        int c = lane + i * 32;
        if (c < C_) outr[c] = v1[i] * r1 + v2[i] * r2;
    }
}

__global__ void zero_counts_kernel() { if (threadIdx.x < E_) g_counts[threadIdx.x] = 0; }
__global__ void write_counts_kernel(float* __restrict__ dst) {
    if (threadIdx.x < E_) dst[threadIdx.x] = (float)g_counts[threadIdx.x];
}

// ---------------------------------------------------------------------------
extern "C" void kernel_launch(void* const* d_in, const int* in_sizes, int n_in,
                              void* d_out, int out_size) {
    const float* x  = (const float*)d_in[0];
    const float* W1 = (const float*)d_in[1];
    const float* b1 = (const float*)d_in[2];
    const float* W2 = (const float*)d_in[3];
    const float* b2 = (const float*)d_in[4];
    const float* Wg = (const float*)d_in[5];
    float* out = (float*)d_out;

    const size_t n_combined = (size_t)B_ * C_;
    const size_t n_preds    = (size_t)E_ * B_ * C_;
    const bool has_preds  = (size_t)out_size >= n_combined + n_preds;
    const bool has_counts = (size_t)out_size >= n_combined + n_preds + E_;
    float* combined  = out;
    float* preds_out = has_preds ? out + n_combined : nullptr;

    zero_counts_kernel<<<1, 32>>>();
    split_x<<<(B_ * F_ / 8) / 256, 256>>>(x);
    split_w1<<<(E_ * H_ * 64) / 256, 256>>>(W1);
    split_w2<<<(E_ * 128 * 32) / 256, 256>>>(W2);
    gate_kernel<<<B_ / 8, 256>>>(x, Wg);

    static bool attr_set = false;
    cudaFuncSetAttribute(mma_gemm<512, 0>, cudaFuncAttributeMaxDynamicSharedMemorySize, 2 * BUFB);
    cudaFuncSetAttribute(mma_gemm<256, 1>, cudaFuncAttributeMaxDynamicSharedMemorySize, 2 * BUFB);
    (void)attr_set;

    mma_gemm<512, 0><<<dim3(2, B_ / 128, E_), 256, 2 * BUFB>>>(b1, nullptr);
    mma_gemm<256, 1><<<dim3(1, B_ / 128, E_), 256, 2 * BUFB>>>(b2, preds_out);

    combine_kernel<<<B_ / 8, 256>>>(preds_out, combined);
    if (has_counts) write_counts_kernel<<<1, 32>>>(out + n_combined + n_preds);
}

// round 5
// speedup vs baseline: 2.9637x; 1.1810x over previous
#include <cuda_runtime.h>
#include <cuda_fp16.h>
#include <cstdint>
#include <math.h>

#define B_ 32768
#define F_ 512
#define H_ 256
#define C_ 100
#define E_ 8

// ---------------- device-global scratch (no allocs allowed) ----------------
__device__ __align__(128) __half g_xH[(size_t)B_ * F_];                  // 32 MB (single, fp16)
__device__ __align__(128) __half g_w1tH[(size_t)E_ * H_ * F_];           // [e][h][f]
__device__ __align__(128) __half g_w1tL[(size_t)E_ * H_ * F_];
__device__ __align__(128) __half g_w2tH[(size_t)E_ * 128 * H_];          // [e][c pad128][h]
__device__ __align__(128) __half g_w2tL[(size_t)E_ * 128 * H_];
__device__ __align__(128) __half g_hH[(size_t)E_ * B_ * H_];             // h split hi
__device__ __align__(128) __half g_hL[(size_t)E_ * B_ * H_];             // h split lo
__device__ float g_preds[(size_t)E_ * B_ * C_];
__device__ int   g_top2[B_];
__device__ int   g_counts[E_];

// ---------------- helpers ----------------
__device__ __forceinline__ uint32_t s2u(const void* p) {
    uint32_t a;
    asm("{ .reg .u64 t; cvta.to.shared.u64 t, %1; cvt.u32.u64 %0, t; }" : "=r"(a) : "l"(p));
    return a;
}
__device__ __forceinline__ uint32_t packh2(float f0, float f1) {
    __half h0 = __float2half_rn(f0), h1 = __float2half_rn(f1);
    return (uint32_t)__half_as_ushort(h0) | ((uint32_t)__half_as_ushort(h1) << 16);
}
__device__ __forceinline__ uint32_t packh2sp(float f0, float f1, uint32_t& lo) {
    __half h0 = __float2half_rn(f0), h1 = __float2half_rn(f1);
    __half l0 = __float2half_rn(f0 - __half2float(h0));
    __half l1 = __float2half_rn(f1 - __half2float(h1));
    lo = (uint32_t)__half_as_ushort(l0) | ((uint32_t)__half_as_ushort(l1) << 16);
    return (uint32_t)__half_as_ushort(h0) | ((uint32_t)__half_as_ushort(h1) << 16);
}
__device__ __forceinline__ void ldm4(uint32_t* r, uint32_t a) {
    asm volatile("ldmatrix.sync.aligned.m8n8.x4.shared.b16 {%0,%1,%2,%3}, [%4];"
                 : "=r"(r[0]), "=r"(r[1]), "=r"(r[2]), "=r"(r[3]) : "r"(a));
}
__device__ __forceinline__ void mma16816(float* c, const uint32_t* a, const uint32_t* b) {
    asm volatile("mma.sync.aligned.m16n8k16.row.col.f32.f16.f16.f32 "
                 "{%0,%1,%2,%3}, {%4,%5,%6,%7}, {%8,%9}, {%0,%1,%2,%3};"
                 : "+f"(c[0]), "+f"(c[1]), "+f"(c[2]), "+f"(c[3])
                 : "r"(a[0]), "r"(a[1]), "r"(a[2]), "r"(a[3]), "r"(b[0]), "r"(b[1]));
}
__device__ __forceinline__ void cpa(uint32_t dst, const void* src) {
    asm volatile("cp.async.cg.shared.global [%0], [%1], 16;" :: "r"(dst), "l"(src));
}

// ---------------- prep kernels ----------------
__global__ __launch_bounds__(256) void split_x(const float* __restrict__ x) {
    size_t gid = (size_t)blockIdx.x * 256 + threadIdx.x;      // B*F/8 threads
    const float4* s = (const float4*)(x + gid * 8);
    float4 f0 = s[0], f1 = s[1];
    uint4 hi;
    hi.x = packh2(f0.x, f0.y); hi.y = packh2(f0.z, f0.w);
    hi.z = packh2(f1.x, f1.y); hi.w = packh2(f1.z, f1.w);
    *(uint4*)(g_xH + gid * 8) = hi;
}
__global__ __launch_bounds__(256) void split_w1(const float* __restrict__ W1) {
    int gid = blockIdx.x * 256 + threadIdx.x;                 // 8*256*64
    int e = gid >> 14, h = (gid >> 6) & 255, f8 = gid & 63;
    float f[8];
#pragma unroll
    for (int j = 0; j < 8; j++) f[j] = W1[((size_t)e * F_ + f8 * 8 + j) * H_ + h];
    uint4 hi, lo;
    hi.x = packh2sp(f[0], f[1], lo.x); hi.y = packh2sp(f[2], f[3], lo.y);
    hi.z = packh2sp(f[4], f[5], lo.z); hi.w = packh2sp(f[6], f[7], lo.w);
    size_t o = ((size_t)e * H_ + h) * F_ + f8 * 8;
    *(uint4*)(g_w1tH + o) = hi;
    *(uint4*)(g_w1tL + o) = lo;
}
__global__ __launch_bounds__(256) void split_w2(const float* __restrict__ W2) {
    int gid = blockIdx.x * 256 + threadIdx.x;                 // 8*128*32
    int e = gid >> 12, c = (gid >> 5) & 127, h8 = gid & 31;
    float f[8];
#pragma unroll
    for (int j = 0; j < 8; j++)
        f[j] = (c < C_) ? W2[((size_t)e * H_ + h8 * 8 + j) * C_ + c] : 0.f;
    uint4 hi, lo;
    hi.x = packh2sp(f[0], f[1], lo.x); hi.y = packh2sp(f[2], f[3], lo.y);
    hi.z = packh2sp(f[4], f[5], lo.z); hi.w = packh2sp(f[6], f[7], lo.w);
    size_t o = ((size_t)e * 128 + c) * H_ + h8 * 8;
    *(uint4*)(g_w2tH + o) = hi;
    *(uint4*)(g_w2tL + o) = lo;
}

// ---------------- HMMA GEMM, fp16 split ----------------
// MODE 0: h = relu(x @ W1^T + b1) -> g_hH/g_hL    (KT=512)  2 terms: xh*(W1h+W1l)
// MODE 1: preds = h @ W2^T + b2                   (KT=256)  3 terms: (hh+hl)*W2h + hh*W2l
// CTA tile 128x128, 8 warps (4M x 2N), warp tile m32n64, Kstage=32, 2-stage cp.async.
#define STRB 80            // smem row stride bytes (40 fp16)
#define ARR 10240          // one [128][40] fp16 array
template <int KT, int MODE>
__global__ void __launch_bounds__(256)
mma_gemm(const float* __restrict__ bias, float* __restrict__ preds_arg) {
    constexpr int NARR = (MODE == 0) ? 3 : 4;
    constexpr int BUF = NARR * ARR;
    extern __shared__ __align__(128) unsigned char sm[];
    const uint32_t sb = s2u(sm);
    const int tid = threadIdx.x, e = blockIdx.z;
    const int n0 = blockIdx.x * 128, m0 = blockIdx.y * 128;

    const __half *s0, *s1, *s2, *s3;
    if (MODE == 0) {
        s0 = g_xH + (size_t)m0 * KT;                               // A (single)
        s1 = g_w1tH + (size_t)e * H_ * F_ + (size_t)n0 * KT;       // Bh
        s2 = g_w1tL + (size_t)e * H_ * F_ + (size_t)n0 * KT;       // Bl
        s3 = nullptr;
    } else {
        s0 = g_hH + (size_t)e * B_ * H_ + (size_t)m0 * KT;         // Ah
        s1 = g_hL + (size_t)e * B_ * H_ + (size_t)m0 * KT;         // Al
        s2 = g_w2tH + (size_t)e * 128 * H_ + (size_t)n0 * KT;      // Bh
        s3 = g_w2tL + (size_t)e * 128 * H_ + (size_t)n0 * KT;      // Bl
    }

    auto load_stage = [&](int buf, int k0) {
#pragma unroll
        for (int j = 0; j < 2; j++) {
            int idx = tid + j * 256;
            int r = idx >> 2, kc = (idx & 3) * 8;
            uint32_t d = sb + buf * BUF + r * STRB + kc * 2;
            size_t off = (size_t)r * KT + k0 + kc;
            cpa(d, s0 + off);
            cpa(d + ARR, s1 + off);
            cpa(d + 2 * ARR, s2 + off);
            if (MODE == 1) cpa(d + 3 * ARR, s3 + off);
        }
        asm volatile("cp.async.commit_group;" ::: "memory");
    };

    const int l = tid & 31, warp = tid >> 5, wr = warp & 3, wc = warp >> 2;
    const uint32_t aOff = (uint32_t)(wr * 32 + (l & 15)) * STRB + (l >> 4) * 16;
    const uint32_t bOff = (uint32_t)(wc * 64 + ((l >> 4) << 3) + (l & 7)) * STRB + ((l >> 3) & 1) * 16;
    constexpr int BO = (MODE == 0) ? 1 : 2;   // B arrays start index

    float acc[2][8][4];
#pragma unroll
    for (int i = 0; i < 2; i++)
#pragma unroll
        for (int j = 0; j < 8; j++)
#pragma unroll
            for (int q = 0; q < 4; q++) acc[i][j][q] = 0.f;

    load_stage(0, 0);
    const int NS = KT / 32;
    for (int s = 0; s < NS; s++) {
        const int buf = s & 1;
        if (s + 1 < NS) {
            load_stage(buf ^ 1, (s + 1) * 32);
            asm volatile("cp.async.wait_group 1;" ::: "memory");
        } else {
            asm volatile("cp.async.wait_group 0;" ::: "memory");
        }
        __syncthreads();
        const uint32_t base = sb + buf * BUF;
#pragma unroll
        for (int h = 0; h < 2; h++) {
            uint32_t ah[2][4], al[2][4];
            ldm4(ah[0], base + aOff + h * 32);
            ldm4(ah[1], base + aOff + 16 * STRB + h * 32);
            if (MODE == 1) {
                ldm4(al[0], base + ARR + aOff + h * 32);
                ldm4(al[1], base + ARR + aOff + 16 * STRB + h * 32);
            }
#pragma unroll
            for (int ni = 0; ni < 4; ni++) {
                uint32_t bh4[4], bl4[4];
                ldm4(bh4, base + BO * ARR + bOff + ni * 16 * STRB + h * 32);
                ldm4(bl4, base + (BO + 1) * ARR + bOff + ni * 16 * STRB + h * 32);
#pragma unroll
                for (int mi = 0; mi < 2; mi++)
#pragma unroll
                    for (int sj = 0; sj < 2; sj++) {
                        float* c = acc[mi][ni * 2 + sj];
                        mma16816(c, ah[mi], bh4 + 2 * sj);
                        mma16816(c, ah[mi], bl4 + 2 * sj);
                        if (MODE == 1) mma16816(c, al[mi], bh4 + 2 * sj);
                    }
            }
        }
        __syncthreads();
    }

    // epilogue: frag c0,c1 -> (row=l/4, col=(l%4)*2 +0/1), c2,c3 -> row+8
    float* preds = preds_arg ? preds_arg : g_preds;
    const float* bsrc = bias + e * (MODE == 0 ? H_ : C_);
#pragma unroll
    for (int mi = 0; mi < 2; mi++) {
        int mB = m0 + wr * 32 + mi * 16 + (l >> 2);
#pragma unroll
        for (int ni = 0; ni < 8; ni++) {
            int n = n0 + wc * 64 + ni * 8 + (l & 3) * 2;
#pragma unroll
            for (int hf = 0; hf < 2; hf++) {
                int m = mB + hf * 8;
                float v0 = acc[mi][ni][hf * 2 + 0];
                float v1 = acc[mi][ni][hf * 2 + 1];
                if (MODE == 0) {
                    v0 = fmaxf(v0 + bsrc[n], 0.f);
                    v1 = fmaxf(v1 + bsrc[n + 1], 0.f);
                    uint32_t lo, hi = packh2sp(v0, v1, lo);
                    size_t o = ((size_t)e * B_ + m) * H_ + n;
                    *(uint32_t*)(g_hH + o) = hi;
                    *(uint32_t*)(g_hL + o) = lo;
                } else {
                    size_t o = ((size_t)e * B_ + m) * C_;
                    if (n < C_)     preds[o + n]     = v0 + bsrc[n];
                    if (n + 1 < C_) preds[o + n + 1] = v1 + bsrc[n + 1];
                }
            }
        }
    }
}

// ---------------- gating ----------------
__global__ __launch_bounds__(256) void gate_kernel(const float* __restrict__ x,
                                                   const float* __restrict__ Wg) {
    __shared__ float wgs[F_ * 9];
    __shared__ int cnt[E_];
    const int tid = threadIdx.x;
    if (tid < E_) cnt[tid] = 0;
    for (int i = tid; i < F_ * E_; i += 256) {
        int f = i >> 3, e = i & 7;
        wgs[f * 9 + e] = Wg[i];
    }
    __syncthreads();
    const int warp = tid >> 5, lane = tid & 31;
    const int row = blockIdx.x * 8 + warp;
    const float* xr = x + (size_t)row * F_;
    float acc[E_];
#pragma unroll
    for (int e = 0; e < E_; e++) acc[e] = 0.f;
#pragma unroll
    for (int i = 0; i < F_ / 32; i++) {
        int f = i * 32 + lane;
        float xv = xr[f];
#pragma unroll
        for (int e = 0; e < E_; e++) acc[e] += xv * wgs[f * 9 + e];
    }
#pragma unroll
    for (int off = 16; off; off >>= 1)
#pragma unroll
        for (int e = 0; e < E_; e++) acc[e] += __shfl_xor_sync(0xffffffffu, acc[e], off);
    if (lane == 0) {
        int i1 = 0;
#pragma unroll
        for (int e = 1; e < E_; e++) if (acc[e] > acc[i1]) i1 = e;
        int i2 = (i1 == 0) ? 1 : 0;
#pragma unroll
        for (int e = 0; e < E_; e++) if (e != i1 && acc[e] > acc[i2]) i2 = e;
        g_top2[row] = i1 | (i2 << 8);
        atomicAdd(&cnt[i1], 1);
        atomicAdd(&cnt[i2], 1);
    }
    __syncthreads();
    if (tid < E_ && cnt[tid]) atomicAdd(&g_counts[tid], cnt[tid]);
}

// ---------------- combine ----------------
__global__ __launch_bounds__(256)
void combine_kernel(const float* __restrict__ preds_arg, float* __restrict__ combined) {
    const float* preds = preds_arg ? preds_arg : g_preds;
    const int warp = threadIdx.x >> 5, lane = threadIdx.x & 31;
    const int row = blockIdx.x * 8 + warp;
    const int packed = g_top2[row];
    const int e1 = packed & 0xFF, e2 = (packed >> 8) & 0xFF;
    const float* p1 = preds + ((size_t)e1 * B_ + row) * C_;
    const float* p2 = preds + ((size_t)e2 * B_ + row) * C_;
    float v1[4], v2[4];
#pragma unroll
    for (int i = 0; i < 4; i++) {
        int c = lane + i * 32;
        bool ok = c < C_;
        v1[i] = ok ? p1[c] : -3.4e38f;
        v2[i] = ok ? p2[c] : -3.4e38f;
    }
    float m1 = fmaxf(fmaxf(v1[0], v1[1]), fmaxf(v1[2], v1[3]));
    float m2 = fmaxf(fmaxf(v2[0], v2[1]), fmaxf(v2[2], v2[3]));
#pragma unroll
    for (int off = 16; off; off >>= 1) {
        m1 = fmaxf(m1, __shfl_xor_sync(0xffffffffu, m1, off));
        m2 = fmaxf(m2, __shfl_xor_sync(0xffffffffu, m2, off));
    }
    float s1 = 0.f, s2 = 0.f;
#pragma unroll
    for (int i = 0; i < 4; i++) {
        int c = lane + i * 32;
        v1[i] = (c < C_) ? expf(v1[i] - m1) : 0.f;
        v2[i] = (c < C_) ? expf(v2[i] - m2) : 0.f;
        s1 += v1[i]; s2 += v2[i];
    }
#pragma unroll
    for (int off = 16; off; off >>= 1) {
        s1 += __shfl_xor_sync(0xffffffffu, s1, off);
        s2 += __shfl_xor_sync(0xffffffffu, s2, off);
    }
    const float r1 = 0.5f / s1, r2 = 0.5f / s2;
    float* outr = combined + (size_t)row * C_;
#pragma unroll
    for (int i = 0; i < 4; i++) {
        int c = lane + i * 32;
        if (c < C_) outr[c] = v1[i] * r1 + v2[i] * r2;
    }
}

__global__ void zero_counts_kernel() { if (threadIdx.x < E_) g_counts[threadIdx.x] = 0; }
__global__ void write_counts_kernel(float* __restrict__ dst) {
    if (threadIdx.x < E_) dst[threadIdx.x] = (float)g_counts[threadIdx.x];
}

// ---------------------------------------------------------------------------
extern "C" void kernel_launch(void* const* d_in, const int* in_sizes, int n_in,
                              void* d_out, int out_size) {
    const float* x  = (const float*)d_in[0];
    const float* W1 = (const float*)d_in[1];
    const float* b1 = (const float*)d_in[2];
    const float* W2 = (const float*)d_in[3];
    const float* b2 = (const float*)d_in[4];
    const float* Wg = (const float*)d_in[5];
    float* out = (float*)d_out;

    const size_t n_combined = (size_t)B_ * C_;
    const size_t n_preds    = (size_t)E_ * B_ * C_;
    const bool has_preds  = (size_t)out_size >= n_combined + n_preds;
    const bool has_counts = (size_t)out_size >= n_combined + n_preds + E_;
    float* combined  = out;
    float* preds_out = has_preds ? out + n_combined : nullptr;

    zero_counts_kernel<<<1, 32>>>();
    split_x<<<(B_ * F_ / 8) / 256, 256>>>(x);
    split_w1<<<(E_ * H_ * 64) / 256, 256>>>(W1);
    split_w2<<<(E_ * 128 * 32) / 256, 256>>>(W2);
    gate_kernel<<<B_ / 8, 256>>>(x, Wg);

    cudaFuncSetAttribute(mma_gemm<512, 0>, cudaFuncAttributeMaxDynamicSharedMemorySize, 2 * 3 * ARR);
    cudaFuncSetAttribute(mma_gemm<256, 1>, cudaFuncAttributeMaxDynamicSharedMemorySize, 2 * 4 * ARR);

    mma_gemm<512, 0><<<dim3(2, B_ / 128, E_), 256, 2 * 3 * ARR>>>(b1, nullptr);
    mma_gemm<256, 1><<<dim3(1, B_ / 128, E_), 256, 2 * 4 * ARR>>>(b2, preds_out);

    combine_kernel<<<B_ / 8, 256>>>(preds_out, combined);
    if (has_counts) write_counts_kernel<<<1, 32>>>(out + n_combined + n_preds);
}

// round 6
// speedup vs baseline: 4.5946x; 1.5503x over previous
#include <cuda_runtime.h>
#include <cuda_fp16.h>
#include <cstdint>
#include <math.h>

#define B_ 32768
#define F_ 512
#define H_ 256
#define C_ 100
#define E_ 8

// ---------------- device-global scratch (no allocs allowed) ----------------
__device__ __align__(128) __half g_xH[(size_t)B_ * F_];           // 32 MB fp16
__device__ __align__(128) __half g_w1tH[(size_t)E_ * H_ * F_];    // [e][h][f] 2 MB
__device__ __align__(128) __half g_w2tH[(size_t)E_ * 128 * H_];   // [e][c pad128][h] 0.5 MB
__device__ float g_preds[(size_t)E_ * B_ * C_];
__device__ int   g_top2[B_];
__device__ int   g_counts[E_];

// ---------------- helpers ----------------
__device__ __forceinline__ uint32_t s2u(const void* p) {
    uint32_t a;
    asm("{ .reg .u64 t; cvta.to.shared.u64 t, %1; cvt.u32.u64 %0, t; }" : "=r"(a) : "l"(p));
    return a;
}
__device__ __forceinline__ uint32_t packh2(float f0, float f1) {
    __half h0 = __float2half_rn(f0), h1 = __float2half_rn(f1);
    return (uint32_t)__half_as_ushort(h0) | ((uint32_t)__half_as_ushort(h1) << 16);
}
__device__ __forceinline__ uint32_t packh2sp(float f0, float f1, uint32_t& lo) {
    __half h0 = __float2half_rn(f0), h1 = __float2half_rn(f1);
    __half l0 = __float2half_rn(f0 - __half2float(h0));
    __half l1 = __float2half_rn(f1 - __half2float(h1));
    lo = (uint32_t)__half_as_ushort(l0) | ((uint32_t)__half_as_ushort(l1) << 16);
    return (uint32_t)__half_as_ushort(h0) | ((uint32_t)__half_as_ushort(h1) << 16);
}
__device__ __forceinline__ void ldm4(uint32_t* r, uint32_t a) {
    asm volatile("ldmatrix.sync.aligned.m8n8.x4.shared.b16 {%0,%1,%2,%3}, [%4];"
                 : "=r"(r[0]), "=r"(r[1]), "=r"(r[2]), "=r"(r[3]) : "r"(a));
}
__device__ __forceinline__ void mma16816(float* c, const uint32_t* a, const uint32_t* b) {
    asm volatile("mma.sync.aligned.m16n8k16.row.col.f32.f16.f16.f32 "
                 "{%0,%1,%2,%3}, {%4,%5,%6,%7}, {%8,%9}, {%0,%1,%2,%3};"
                 : "+f"(c[0]), "+f"(c[1]), "+f"(c[2]), "+f"(c[3])
                 : "r"(a[0]), "r"(a[1]), "r"(a[2]), "r"(a[3]), "r"(b[0]), "r"(b[1]));
}
__device__ __forceinline__ void cpa(uint32_t dst, const void* src) {
    asm volatile("cp.async.cg.shared.global [%0], [%1], 16;" :: "r"(dst), "l"(src));
}

// ---------------- prep kernels (single fp16) ----------------
__global__ __launch_bounds__(256) void split_x(const float* __restrict__ x) {
    size_t gid = (size_t)blockIdx.x * 256 + threadIdx.x;
    const float4* s = (const float4*)(x + gid * 8);
    float4 f0 = s[0], f1 = s[1];
    uint4 hi;
    hi.x = packh2(f0.x, f0.y); hi.y = packh2(f0.z, f0.w);
    hi.z = packh2(f1.x, f1.y); hi.w = packh2(f1.z, f1.w);
    *(uint4*)(g_xH + gid * 8) = hi;
}
__global__ __launch_bounds__(256) void split_w1(const float* __restrict__ W1) {
    int gid = blockIdx.x * 256 + threadIdx.x;                 // 8*256*64
    int e = gid >> 14, h = (gid >> 6) & 255, f8 = gid & 63;
    float f[8];
#pragma unroll
    for (int j = 0; j < 8; j++) f[j] = W1[((size_t)e * F_ + f8 * 8 + j) * H_ + h];
    uint4 hi;
    hi.x = packh2(f[0], f[1]); hi.y = packh2(f[2], f[3]);
    hi.z = packh2(f[4], f[5]); hi.w = packh2(f[6], f[7]);
    *(uint4*)(g_w1tH + ((size_t)e * H_ + h) * F_ + f8 * 8) = hi;
}
__global__ __launch_bounds__(256) void split_w2(const float* __restrict__ W2) {
    int gid = blockIdx.x * 256 + threadIdx.x;                 // 8*128*32
    int e = gid >> 12, c = (gid >> 5) & 127, h8 = gid & 31;
    float f[8];
#pragma unroll
    for (int j = 0; j < 8; j++)
        f[j] = (c < C_) ? W2[((size_t)e * H_ + h8 * 8 + j) * C_ + c] : 0.f;
    uint4 hi;
    hi.x = packh2(f[0], f[1]); hi.y = packh2(f[2], f[3]);
    hi.z = packh2(f[4], f[5]); hi.w = packh2(f[6], f[7]);
    *(uint4*)(g_w2tH + ((size_t)e * 128 + c) * H_ + h8 * 8) = hi;
}

// ---------------- fused expert kernel ----------------
// Per (mtile, e): GEMM1 (1-term): h[128,256] = relu(x@W1^T + b1), acc fp32,
//   epilogue re-split to fp16 hi/lo in SMEM; GEMM2 (2-term): preds = (hh+hl)@W2h^T + b2.
// 512 threads = 16 warps: GEMM1 warp tile m32n64 (4x4), GEMM2 m32n32 (4x4).
#define A1SZ 10240                 // A stage array: 128 x 80B
#define STG1 30720                 // GEMM1 stage buf: A + B(256x80B)
#define HSTR 528                   // h row stride bytes (264 halves; 132 words -> conflict-free)
#define HHI  61440
#define HLO  129024
#define SMEM_TOT 196608

__global__ void __launch_bounds__(512, 1)
fused_moe(const float* __restrict__ b1g, const float* __restrict__ b2g,
          float* __restrict__ preds_arg) {
    extern __shared__ __align__(128) unsigned char sm[];
    const uint32_t sb = s2u(sm);
    const int tid = threadIdx.x;
    const int m0 = blockIdx.x * 128, e = blockIdx.y;
    float* preds = preds_arg ? preds_arg : g_preds;

    const __half* Asrc = g_xH + (size_t)m0 * F_;
    const __half* Bsrc = g_w1tH + (size_t)e * H_ * F_;
    const __half* Wsrc = g_w2tH + (size_t)e * 128 * H_;

    const int l = tid & 31, warp = tid >> 5, wr = warp & 3, wc = warp >> 2;

    auto load1 = [&](int buf, int k0) {
        {   // A: 128 rows x 32k, one 16B chunk per thread
            int r = tid >> 2, kc = (tid & 3) * 8;
            cpa(sb + buf * STG1 + r * 80 + kc * 2, Asrc + (size_t)r * F_ + k0 + kc);
        }
#pragma unroll
        for (int j = 0; j < 2; j++) {   // B: 256 rows x 32k
            int idx = tid + j * 512;
            int r = idx >> 2, kc = (idx & 3) * 8;
            cpa(sb + buf * STG1 + A1SZ + r * 80 + kc * 2, Bsrc + (size_t)r * F_ + k0 + kc);
        }
        asm volatile("cp.async.commit_group;" ::: "memory");
    };
    auto load2 = [&](int buf, int k0) {   // W2h: 128 rows x 32k
        int r = tid >> 2, kc = (tid & 3) * 8;
        cpa(sb + buf * A1SZ + r * 80 + kc * 2, Wsrc + (size_t)r * H_ + k0 + kc);
        asm volatile("cp.async.commit_group;" ::: "memory");
    };

    // ---------------- GEMM1 ----------------
    const uint32_t aOff = (uint32_t)(wr * 32 + (l & 15)) * 80 + (l >> 4) * 16;
    const uint32_t bOff = (uint32_t)(wc * 64 + ((l >> 4) << 3) + (l & 7)) * 80 + ((l >> 3) & 1) * 16;

    float acc[2][8][4];
#pragma unroll
    for (int i = 0; i < 2; i++)
#pragma unroll
        for (int j = 0; j < 8; j++)
#pragma unroll
            for (int q = 0; q < 4; q++) acc[i][j][q] = 0.f;

    load1(0, 0);
    const int NS1 = F_ / 32;   // 16
    for (int s = 0; s < NS1; s++) {
        const int buf = s & 1;
        if (s + 1 < NS1) {
            load1(buf ^ 1, (s + 1) * 32);
            asm volatile("cp.async.wait_group 1;" ::: "memory");
        } else {
            asm volatile("cp.async.wait_group 0;" ::: "memory");
        }
        __syncthreads();
        const uint32_t base = sb + buf * STG1;
#pragma unroll
        for (int h = 0; h < 2; h++) {
            uint32_t a4[2][4];
            ldm4(a4[0], base + aOff + h * 32);
            ldm4(a4[1], base + aOff + 16 * 80 + h * 32);
#pragma unroll
            for (int ni = 0; ni < 4; ni++) {
                uint32_t b4[4];
                ldm4(b4, base + A1SZ + bOff + ni * 16 * 80 + h * 32);
#pragma unroll
                for (int mi = 0; mi < 2; mi++)
#pragma unroll
                    for (int sj = 0; sj < 2; sj++)
                        mma16816(acc[mi][ni * 2 + sj], a4[mi], b4 + 2 * sj);
            }
        }
        __syncthreads();
    }

    // prefetch W2 stage 0 into freed GEMM1 buf0 region, overlap with epilogue
    load2(0, 0);

    // ---------------- epilogue 1: relu(+b1) -> fp16 hi/lo in SMEM ----------------
    {
        const float* bs1 = b1g + e * H_;
#pragma unroll
        for (int mi = 0; mi < 2; mi++) {
            int rB = wr * 32 + mi * 16 + (l >> 2);
#pragma unroll
            for (int ni = 0; ni < 8; ni++) {
                int n = wc * 64 + ni * 8 + (l & 3) * 2;
#pragma unroll
                for (int hf = 0; hf < 2; hf++) {
                    int r = rB + hf * 8;
                    float v0 = fmaxf(acc[mi][ni][hf * 2 + 0] + bs1[n], 0.f);
                    float v1 = fmaxf(acc[mi][ni][hf * 2 + 1] + bs1[n + 1], 0.f);
                    uint32_t lo, hi = packh2sp(v0, v1, lo);
                    *(uint32_t*)(sm + HHI + r * HSTR + n * 2) = hi;
                    *(uint32_t*)(sm + HLO + r * HSTR + n * 2) = lo;
                }
            }
        }
    }

    // ---------------- GEMM2: (hh + hl) @ W2h^T ----------------
    const uint32_t a2Off = (uint32_t)(wr * 32 + (l & 15)) * HSTR + (l >> 4) * 16;
    const uint32_t b2Off = (uint32_t)(wc * 32 + ((l >> 4) << 3) + (l & 7)) * 80 + ((l >> 3) & 1) * 16;

    float acc2[2][4][4];
#pragma unroll
    for (int i = 0; i < 2; i++)
#pragma unroll
        for (int j = 0; j < 4; j++)
#pragma unroll
            for (int q = 0; q < 4; q++) acc2[i][j][q] = 0.f;

    const int NS2 = H_ / 32;   // 8
    for (int s = 0; s < NS2; s++) {
        const int buf = s & 1;
        if (s + 1 < NS2) {
            load2(buf ^ 1, (s + 1) * 32);
            asm volatile("cp.async.wait_group 1;" ::: "memory");
        } else {
            asm volatile("cp.async.wait_group 0;" ::: "memory");
        }
        __syncthreads();   // also publishes h on s=0
        const uint32_t wbase = sb + buf * A1SZ;
#pragma unroll
        for (int h = 0; h < 2; h++) {
            uint32_t ah[2][4], al[2][4];
            ldm4(ah[0], sb + HHI + a2Off + s * 64 + h * 32);
            ldm4(ah[1], sb + HHI + a2Off + 16 * HSTR + s * 64 + h * 32);
            ldm4(al[0], sb + HLO + a2Off + s * 64 + h * 32);
            ldm4(al[1], sb + HLO + a2Off + 16 * HSTR + s * 64 + h * 32);
#pragma unroll
            for (int ni = 0; ni < 2; ni++) {
                uint32_t b4[4];
                ldm4(b4, wbase + b2Off + ni * 16 * 80 + h * 32);
#pragma unroll
                for (int mi = 0; mi < 2; mi++)
#pragma unroll
                    for (int sj = 0; sj < 2; sj++) {
                        mma16816(acc2[mi][ni * 2 + sj], ah[mi], b4 + 2 * sj);
                        mma16816(acc2[mi][ni * 2 + sj], al[mi], b4 + 2 * sj);
                    }
            }
        }
        __syncthreads();
    }

    // ---------------- epilogue 2: + b2 -> preds ----------------
    {
        const float* bs2 = b2g + e * C_;
#pragma unroll
        for (int mi = 0; mi < 2; mi++) {
            int mB = m0 + wr * 32 + mi * 16 + (l >> 2);
#pragma unroll
            for (int ni = 0; ni < 4; ni++) {
                int n = wc * 32 + ni * 8 + (l & 3) * 2;
#pragma unroll
                for (int hf = 0; hf < 2; hf++) {
                    int m = mB + hf * 8;
                    size_t o = ((size_t)e * B_ + m) * C_;
                    if (n < C_)     preds[o + n]     = acc2[mi][ni][hf * 2 + 0] + bs2[n];
                    if (n + 1 < C_) preds[o + n + 1] = acc2[mi][ni][hf * 2 + 1] + bs2[n + 1];
                }
            }
        }
    }
}

// ---------------- gating ----------------
__global__ __launch_bounds__(256) void gate_kernel(const float* __restrict__ x,
                                                   const float* __restrict__ Wg) {
    __shared__ float wgs[F_ * 9];
    __shared__ int cnt[E_];
    const int tid = threadIdx.x;
    if (tid < E_) cnt[tid] = 0;
    for (int i = tid; i < F_ * E_; i += 256) {
        int f = i >> 3, e = i & 7;
        wgs[f * 9 + e] = Wg[i];
    }
    __syncthreads();
    const int warp = tid >> 5, lane = tid & 31;
    const int row = blockIdx.x * 8 + warp;
    const float* xr = x + (size_t)row * F_;
    float acc[E_];
#pragma unroll
    for (int e = 0; e < E_; e++) acc[e] = 0.f;
#pragma unroll
    for (int i = 0; i < F_ / 32; i++) {
        int f = i * 32 + lane;
        float xv = xr[f];
#pragma unroll
        for (int e = 0; e < E_; e++) acc[e] += xv * wgs[f * 9 + e];
    }
#pragma unroll
    for (int off = 16; off; off >>= 1)
#pragma unroll
        for (int e = 0; e < E_; e++) acc[e] += __shfl_xor_sync(0xffffffffu, acc[e], off);
    if (lane == 0) {
        int i1 = 0;
#pragma unroll
        for (int e = 1; e < E_; e++) if (acc[e] > acc[i1]) i1 = e;
        int i2 = (i1 == 0) ? 1 : 0;
#pragma unroll
        for (int e = 0; e < E_; e++) if (e != i1 && acc[e] > acc[i2]) i2 = e;
        g_top2[row] = i1 | (i2 << 8);
        atomicAdd(&cnt[i1], 1);
        atomicAdd(&cnt[i2], 1);
    }
    __syncthreads();
    if (tid < E_ && cnt[tid]) atomicAdd(&g_counts[tid], cnt[tid]);
}

// ---------------- combine ----------------
__global__ __launch_bounds__(256)
void combine_kernel(const float* __restrict__ preds_arg, float* __restrict__ combined) {
    const float* preds = preds_arg ? preds_arg : g_preds;
    const int warp = threadIdx.x >> 5, lane = threadIdx.x & 31;
    const int row = blockIdx.x * 8 + warp;
    const int packed = g_top2[row];
    const int e1 = packed & 0xFF, e2 = (packed >> 8) & 0xFF;
    const float* p1 = preds + ((size_t)e1 * B_ + row) * C_;
    const float* p2 = preds + ((size_t)e2 * B_ + row) * C_;
    float v1[4], v2[4];
#pragma unroll
    for (int i = 0; i < 4; i++) {
        int c = lane + i * 32;
        bool ok = c < C_;
        v1[i] = ok ? p1[c] : -3.4e38f;
        v2[i] = ok ? p2[c] : -3.4e38f;
    }
    float m1 = fmaxf(fmaxf(v1[0], v1[1]), fmaxf(v1[2], v1[3]));
    float m2 = fmaxf(fmaxf(v2[0], v2[1]), fmaxf(v2[2], v2[3]));
#pragma unroll
    for (int off = 16; off; off >>= 1) {
        m1 = fmaxf(m1, __shfl_xor_sync(0xffffffffu, m1, off));
        m2 = fmaxf(m2, __shfl_xor_sync(0xffffffffu, m2, off));
    }
    float s1 = 0.f, s2 = 0.f;
#pragma unroll
    for (int i = 0; i < 4; i++) {
        int c = lane + i * 32;
        v1[i] = (c < C_) ? expf(v1[i] - m1) : 0.f;
        v2[i] = (c < C_) ? expf(v2[i] - m2) : 0.f;
        s1 += v1[i]; s2 += v2[i];
    }
#pragma unroll
    for (int off = 16; off; off >>= 1) {
        s1 += __shfl_xor_sync(0xffffffffu, s1, off);
        s2 += __shfl_xor_sync(0xffffffffu, s2, off);
    }
    const float r1 = 0.5f / s1, r2 = 0.5f / s2;
    float* outr = combined + (size_t)row * C_;
#pragma unroll
    for (int i = 0; i < 4; i++) {
        int c = lane + i * 32;
        if (c < C_) outr[c] = v1[i] * r1 + v2[i] * r2;
    }
}

__global__ void zero_counts_kernel() { if (threadIdx.x < E_) g_counts[threadIdx.x] = 0; }
__global__ void write_counts_kernel(float* __restrict__ dst) {
    if (threadIdx.x < E_) dst[threadIdx.x] = (float)g_counts[threadIdx.x];
}

// ---------------------------------------------------------------------------
extern "C" void kernel_launch(void* const* d_in, const int* in_sizes, int n_in,
                              void* d_out, int out_size) {
    const float* x  = (const float*)d_in[0];
    const float* W1 = (const float*)d_in[1];
    const float* b1 = (const float*)d_in[2];
    const float* W2 = (const float*)d_in[3];
    const float* b2 = (const float*)d_in[4];
    const float* Wg = (const float*)d_in[5];
    float* out = (float*)d_out;

    const size_t n_combined = (size_t)B_ * C_;
    const size_t n_preds    = (size_t)E_ * B_ * C_;
    const bool has_preds  = (size_t)out_size >= n_combined + n_preds;
    const bool has_counts = (size_t)out_size >= n_combined + n_preds + E_;
    float* combined  = out;
    float* preds_out = has_preds ? out + n_combined : nullptr;

    zero_counts_kernel<<<1, 32>>>();
    split_x<<<(B_ * F_ / 8) / 256, 256>>>(x);
    split_w1<<<(E_ * H_ * 64) / 256, 256>>>(W1);
    split_w2<<<(E_ * 128 * 32) / 256, 256>>>(W2);
    gate_kernel<<<B_ / 8, 256>>>(x, Wg);

    cudaFuncSetAttribute(fused_moe, cudaFuncAttributeMaxDynamicSharedMemorySize, SMEM_TOT);
    fused_moe<<<dim3(B_ / 128, E_), 512, SMEM_TOT>>>(b1, b2, preds_out);

    combine_kernel<<<B_ / 8, 256>>>(preds_out, combined);
    if (has_counts) write_counts_kernel<<<1, 32>>>(out + n_combined + n_preds);
}

// round 7
// speedup vs baseline: 4.9847x; 1.0849x over previous
#include <cuda_runtime.h>
#include <cuda_fp16.h>
#include <cstdint>
#include <math.h>

#define B_ 32768
#define F_ 512
#define H_ 256
#define C_ 100
#define E_ 8

// ---------------- device-global scratch (no allocs allowed) ----------------
__device__ __align__(128) __half g_xH[(size_t)B_ * F_];           // 32 MB fp16
__device__ __align__(128) __half g_w1tH[(size_t)E_ * H_ * F_];    // [e][h][f] 2 MB
__device__ __align__(128) __half g_w2tH[(size_t)E_ * 128 * H_];   // [e][c pad128][h] 0.5 MB
__device__ float g_preds[(size_t)E_ * B_ * C_];
__device__ int   g_top2[B_];
__device__ int   g_counts[E_];

// ---------------- helpers ----------------
__device__ __forceinline__ uint32_t s2u(const void* p) {
    uint32_t a;
    asm("{ .reg .u64 t; cvta.to.shared.u64 t, %1; cvt.u32.u64 %0, t; }" : "=r"(a) : "l"(p));
    return a;
}
__device__ __forceinline__ uint32_t packh2(float f0, float f1) {
    __half h0 = __float2half_rn(f0), h1 = __float2half_rn(f1);
    return (uint32_t)__half_as_ushort(h0) | ((uint32_t)__half_as_ushort(h1) << 16);
}
__device__ __forceinline__ void ldm4(uint32_t* r, uint32_t a) {
    asm volatile("ldmatrix.sync.aligned.m8n8.x4.shared.b16 {%0,%1,%2,%3}, [%4];"
                 : "=r"(r[0]), "=r"(r[1]), "=r"(r[2]), "=r"(r[3]) : "r"(a));
}
__device__ __forceinline__ void mma16816(float* c, const uint32_t* a, const uint32_t* b) {
    asm volatile("mma.sync.aligned.m16n8k16.row.col.f32.f16.f16.f32 "
                 "{%0,%1,%2,%3}, {%4,%5,%6,%7}, {%8,%9}, {%0,%1,%2,%3};"
                 : "+f"(c[0]), "+f"(c[1]), "+f"(c[2]), "+f"(c[3])
                 : "r"(a[0]), "r"(a[1]), "r"(a[2]), "r"(a[3]), "r"(b[0]), "r"(b[1]));
}
__device__ __forceinline__ void cpa(uint32_t dst, const void* src) {
    asm volatile("cp.async.cg.shared.global [%0], [%1], 16;" :: "r"(dst), "l"(src));
}

// ---------------- merged prep kernel (fp32 -> fp16) ----------------
// blocks [0, 8192)        : x      (B*F/8 = 2M elems of 8 floats)
// blocks [8192, 8704)     : W1^T   (8*256*64 threads)
// blocks [8704, 8832)     : W2^T   (8*128*32 threads)
__global__ __launch_bounds__(256) void prep_all(const float* __restrict__ x,
                                                const float* __restrict__ W1,
                                                const float* __restrict__ W2) {
    int bid = blockIdx.x;
    if (bid < 8192) {
        size_t gid = (size_t)bid * 256 + threadIdx.x;
        const float4* s = (const float4*)(x + gid * 8);
        float4 f0 = s[0], f1 = s[1];
        uint4 hi;
        hi.x = packh2(f0.x, f0.y); hi.y = packh2(f0.z, f0.w);
        hi.z = packh2(f1.x, f1.y); hi.w = packh2(f1.z, f1.w);
        *(uint4*)(g_xH + gid * 8) = hi;
    } else if (bid < 8704) {
        int gid = (bid - 8192) * 256 + threadIdx.x;           // 8*256*64
        int e = gid >> 14, h = (gid >> 6) & 255, f8 = gid & 63;
        float f[8];
#pragma unroll
        for (int j = 0; j < 8; j++) f[j] = W1[((size_t)e * F_ + f8 * 8 + j) * H_ + h];
        uint4 hi;
        hi.x = packh2(f[0], f[1]); hi.y = packh2(f[2], f[3]);
        hi.z = packh2(f[4], f[5]); hi.w = packh2(f[6], f[7]);
        *(uint4*)(g_w1tH + ((size_t)e * H_ + h) * F_ + f8 * 8) = hi;
    } else {
        int gid = (bid - 8704) * 256 + threadIdx.x;           // 8*128*32
        int e = gid >> 12, c = (gid >> 5) & 127, h8 = gid & 31;
        float f[8];
#pragma unroll
        for (int j = 0; j < 8; j++)
            f[j] = (c < C_) ? W2[((size_t)e * H_ + h8 * 8 + j) * C_ + c] : 0.f;
        uint4 hi;
        hi.x = packh2(f[0], f[1]); hi.y = packh2(f[2], f[3]);
        hi.z = packh2(f[4], f[5]); hi.w = packh2(f[6], f[7]);
        *(uint4*)(g_w2tH + ((size_t)e * 128 + c) * H_ + h8 * 8) = hi;
    }
}

// ---------------- fused expert kernel ----------------
// Per (mtile, e): GEMM1 (1-term): h[128,256] = relu(x@W1^T + b1), fp32 acc,
//   epilogue -> fp16 h in SMEM; GEMM2 (1-term): preds = h@W2h^T + b2.
// 512 threads = 16 warps: GEMM1 warp tile m32n64 (4x4), GEMM2 m32n32 (4x4).
#define A1SZ 10240                 // one stage array: 128 x 80B
#define STG1 30720                 // GEMM1 stage buf: A + B(256x80B)
#define HSTR 528                   // h row stride bytes (264 halves; conflict-free)
#define HHI  61440
#define SMEM_TOT 129024            // 61440 staging + 128*528 h

__global__ void __launch_bounds__(512, 1)
fused_moe(const float* __restrict__ b1g, const float* __restrict__ b2g,
          float* __restrict__ preds_arg) {
    extern __shared__ __align__(128) unsigned char sm[];
    const uint32_t sb = s2u(sm);
    const int tid = threadIdx.x;
    const int m0 = blockIdx.x * 128, e = blockIdx.y;
    float* preds = preds_arg ? preds_arg : g_preds;

    const __half* Asrc = g_xH + (size_t)m0 * F_;
    const __half* Bsrc = g_w1tH + (size_t)e * H_ * F_;
    const __half* Wsrc = g_w2tH + (size_t)e * 128 * H_;

    const int l = tid & 31, warp = tid >> 5, wr = warp & 3, wc = warp >> 2;

    auto load1 = [&](int buf, int k0) {
        {   // A: 128 rows x 32k
            int r = tid >> 2, kc = (tid & 3) * 8;
            cpa(sb + buf * STG1 + r * 80 + kc * 2, Asrc + (size_t)r * F_ + k0 + kc);
        }
#pragma unroll
        for (int j = 0; j < 2; j++) {   // B: 256 rows x 32k
            int idx = tid + j * 512;
            int r = idx >> 2, kc = (idx & 3) * 8;
            cpa(sb + buf * STG1 + A1SZ + r * 80 + kc * 2, Bsrc + (size_t)r * F_ + k0 + kc);
        }
        asm volatile("cp.async.commit_group;" ::: "memory");
    };
    auto load2 = [&](int buf, int k0) {   // W2h: 128 rows x 32k
        int r = tid >> 2, kc = (tid & 3) * 8;
        cpa(sb + buf * A1SZ + r * 80 + kc * 2, Wsrc + (size_t)r * H_ + k0 + kc);
        asm volatile("cp.async.commit_group;" ::: "memory");
    };

    // ---------------- GEMM1 ----------------
    const uint32_t aOff = (uint32_t)(wr * 32 + (l & 15)) * 80 + (l >> 4) * 16;
    const uint32_t bOff = (uint32_t)(wc * 64 + ((l >> 4) << 3) + (l & 7)) * 80 + ((l >> 3) & 1) * 16;

    float acc[2][8][4];
#pragma unroll
    for (int i = 0; i < 2; i++)
#pragma unroll
        for (int j = 0; j < 8; j++)
#pragma unroll
            for (int q = 0; q < 4; q++) acc[i][j][q] = 0.f;

    load1(0, 0);
    const int NS1 = F_ / 32;   // 16
    for (int s = 0; s < NS1; s++) {
        const int buf = s & 1;
        if (s + 1 < NS1) {
            load1(buf ^ 1, (s + 1) * 32);
            asm volatile("cp.async.wait_group 1;" ::: "memory");
        } else {
            asm volatile("cp.async.wait_group 0;" ::: "memory");
        }
        __syncthreads();
        const uint32_t base = sb + buf * STG1;
#pragma unroll
        for (int h = 0; h < 2; h++) {
            uint32_t a4[2][4];
            ldm4(a4[0], base + aOff + h * 32);
            ldm4(a4[1], base + aOff + 16 * 80 + h * 32);
#pragma unroll
            for (int ni = 0; ni < 4; ni++) {
                uint32_t b4[4];
                ldm4(b4, base + A1SZ + bOff + ni * 16 * 80 + h * 32);
#pragma unroll
                for (int mi = 0; mi < 2; mi++)
#pragma unroll
                    for (int sj = 0; sj < 2; sj++)
                        mma16816(acc[mi][ni * 2 + sj], a4[mi], b4 + 2 * sj);
            }
        }
        __syncthreads();
    }

    // prefetch W2 stage 0 into freed GEMM1 buf0 region, overlap with epilogue
    load2(0, 0);

    // ---------------- epilogue 1: relu(+b1) -> fp16 h in SMEM ----------------
    {
        const float* bs1 = b1g + e * H_;
#pragma unroll
        for (int mi = 0; mi < 2; mi++) {
            int rB = wr * 32 + mi * 16 + (l >> 2);
#pragma unroll
            for (int ni = 0; ni < 8; ni++) {
                int n = wc * 64 + ni * 8 + (l & 3) * 2;
#pragma unroll
                for (int hf = 0; hf < 2; hf++) {
                    int r = rB + hf * 8;
                    float v0 = fmaxf(acc[mi][ni][hf * 2 + 0] + bs1[n], 0.f);
                    float v1 = fmaxf(acc[mi][ni][hf * 2 + 1] + bs1[n + 1], 0.f);
                    *(uint32_t*)(sm + HHI + r * HSTR + n * 2) = packh2(v0, v1);
                }
            }
        }
    }

    // ---------------- GEMM2: h @ W2h^T (1 term) ----------------
    const uint32_t a2Off = (uint32_t)(wr * 32 + (l & 15)) * HSTR + (l >> 4) * 16;
    const uint32_t b2Off = (uint32_t)(wc * 32 + ((l >> 4) << 3) + (l & 7)) * 80 + ((l >> 3) & 1) * 16;

    float acc2[2][4][4];
#pragma unroll
    for (int i = 0; i < 2; i++)
#pragma unroll
        for (int j = 0; j < 4; j++)
#pragma unroll
            for (int q = 0; q < 4; q++) acc2[i][j][q] = 0.f;

    const int NS2 = H_ / 32;   // 8
    for (int s = 0; s < NS2; s++) {
        const int buf = s & 1;
        if (s + 1 < NS2) {
            load2(buf ^ 1, (s + 1) * 32);
            asm volatile("cp.async.wait_group 1;" ::: "memory");
        } else {
            asm volatile("cp.async.wait_group 0;" ::: "memory");
        }
        __syncthreads();   // also publishes h on s=0
        const uint32_t wbase = sb + buf * A1SZ;
#pragma unroll
        for (int h = 0; h < 2; h++) {
            uint32_t ah[2][4];
            ldm4(ah[0], sb + HHI + a2Off + s * 64 + h * 32);
            ldm4(ah[1], sb + HHI + a2Off + 16 * HSTR + s * 64 + h * 32);
#pragma unroll
            for (int ni = 0; ni < 2; ni++) {
                uint32_t b4[4];
                ldm4(b4, wbase + b2Off + ni * 16 * 80 + h * 32);
#pragma unroll
                for (int mi = 0; mi < 2; mi++)
#pragma unroll
                    for (int sj = 0; sj < 2; sj++)
                        mma16816(acc2[mi][ni * 2 + sj], ah[mi], b4 + 2 * sj);
            }
        }
        __syncthreads();
    }

    // ---------------- epilogue 2: + b2 -> preds ----------------
    {
        const float* bs2 = b2g + e * C_;
#pragma unroll
        for (int mi = 0; mi < 2; mi++) {
            int mB = m0 + wr * 32 + mi * 16 + (l >> 2);
#pragma unroll
            for (int ni = 0; ni < 4; ni++) {
                int n = wc * 32 + ni * 8 + (l & 3) * 2;
#pragma unroll
                for (int hf = 0; hf < 2; hf++) {
                    int m = mB + hf * 8;
                    size_t o = ((size_t)e * B_ + m) * C_;
                    if (n < C_)     preds[o + n]     = acc2[mi][ni][hf * 2 + 0] + bs2[n];
                    if (n + 1 < C_) preds[o + n + 1] = acc2[mi][ni][hf * 2 + 1] + bs2[n + 1];
                }
            }
        }
    }
}

// ---------------- gating ----------------
__global__ __launch_bounds__(256) void gate_kernel(const float* __restrict__ x,
                                                   const float* __restrict__ Wg) {
    __shared__ float wgs[F_ * 9];
    __shared__ int cnt[E_];
    const int tid = threadIdx.x;
    if (tid < E_) cnt[tid] = 0;
    for (int i = tid; i < F_ * E_; i += 256) {
        int f = i >> 3, e = i & 7;
        wgs[f * 9 + e] = Wg[i];
    }
    __syncthreads();
    const int warp = tid >> 5, lane = tid & 31;
    const int row = blockIdx.x * 8 + warp;
    const float* xr = x + (size_t)row * F_;
    float acc[E_];
#pragma unroll
    for (int e = 0; e < E_; e++) acc[e] = 0.f;
#pragma unroll
    for (int i = 0; i < F_ / 32; i++) {
        int f = i * 32 + lane;
        float xv = xr[f];
#pragma unroll
        for (int e = 0; e < E_; e++) acc[e] += xv * wgs[f * 9 + e];
    }
#pragma unroll
    for (int off = 16; off; off >>= 1)
#pragma unroll
        for (int e = 0; e < E_; e++) acc[e] += __shfl_xor_sync(0xffffffffu, acc[e], off);
    if (lane == 0) {
        int i1 = 0;
#pragma unroll
        for (int e = 1; e < E_; e++) if (acc[e] > acc[i1]) i1 = e;
        int i2 = (i1 == 0) ? 1 : 0;
#pragma unroll
        for (int e = 0; e < E_; e++) if (e != i1 && acc[e] > acc[i2]) i2 = e;
        g_top2[row] = i1 | (i2 << 8);
        atomicAdd(&cnt[i1], 1);
        atomicAdd(&cnt[i2], 1);
    }
    __syncthreads();
    if (tid < E_ && cnt[tid]) atomicAdd(&g_counts[tid], cnt[tid]);
}

// ---------------- combine ----------------
__global__ __launch_bounds__(256)
void combine_kernel(const float* __restrict__ preds_arg, float* __restrict__ combined) {
    const float* preds = preds_arg ? preds_arg : g_preds;
    const int warp = threadIdx.x >> 5, lane = threadIdx.x & 31;
    const int row = blockIdx.x * 8 + warp;
    const int packed = g_top2[row];
    const int e1 = packed & 0xFF, e2 = (packed >> 8) & 0xFF;
    const float* p1 = preds + ((size_t)e1 * B_ + row) * C_;
    const float* p2 = preds + ((size_t)e2 * B_ + row) * C_;
    float v1[4], v2[4];
#pragma unroll
    for (int i = 0; i < 4; i++) {
        int c = lane + i * 32;
        bool ok = c < C_;
        v1[i] = ok ? p1[c] : -3.4e38f;
        v2[i] = ok ? p2[c] : -3.4e38f;
    }
    float m1 = fmaxf(fmaxf(v1[0], v1[1]), fmaxf(v1[2], v1[3]));
    float m2 = fmaxf(fmaxf(v2[0], v2[1]), fmaxf(v2[2], v2[3]));
#pragma unroll
    for (int off = 16; off; off >>= 1) {
        m1 = fmaxf(m1, __shfl_xor_sync(0xffffffffu, m1, off));
        m2 = fmaxf(m2, __shfl_xor_sync(0xffffffffu, m2, off));
    }
    float s1 = 0.f, s2 = 0.f;
#pragma unroll
    for (int i = 0; i < 4; i++) {
        int c = lane + i * 32;
        v1[i] = (c < C_) ? expf(v1[i] - m1) : 0.f;
        v2[i] = (c < C_) ? expf(v2[i] - m2) : 0.f;
        s1 += v1[i]; s2 += v2[i];
    }
#pragma unroll
    for (int off = 16; off; off >>= 1) {
        s1 += __shfl_xor_sync(0xffffffffu, s1, off);
        s2 += __shfl_xor_sync(0xffffffffu, s2, off);
    }
    const float r1 = 0.5f / s1, r2 = 0.5f / s2;
    float* outr = combined + (size_t)row * C_;
#pragma unroll
    for (int i = 0; i < 4; i++) {
        int c = lane + i * 32;
        if (c < C_) outr[c] = v1[i] * r1 + v2[i] * r2;
    }
}

__global__ void zero_counts_kernel() { if (threadIdx.x < E_) g_counts[threadIdx.x] = 0; }
__global__ void write_counts_kernel(float* __restrict__ dst) {
    if (threadIdx.x < E_) dst[threadIdx.x] = (float)g_counts[threadIdx.x];
}

// ---------------------------------------------------------------------------
extern "C" void kernel_launch(void* const* d_in, const int* in_sizes, int n_in,
                              void* d_out, int out_size) {
    const float* x  = (const float*)d_in[0];
    const float* W1 = (const float*)d_in[1];
    const float* b1 = (const float*)d_in[2];
    const float* W2 = (const float*)d_in[3];
    const float* b2 = (const float*)d_in[4];
    const float* Wg = (const float*)d_in[5];
    float* out = (float*)d_out;

    const size_t n_combined = (size_t)B_ * C_;
    const size_t n_preds    = (size_t)E_ * B_ * C_;
    const bool has_preds  = (size_t)out_size >= n_combined + n_preds;
    const bool has_counts = (size_t)out_size >= n_combined + n_preds + E_;
    float* combined  = out;
    float* preds_out = has_preds ? out + n_combined : nullptr;

    zero_counts_kernel<<<1, 32>>>();
    prep_all<<<8832, 256>>>(x, W1, W2);
    gate_kernel<<<B_ / 8, 256>>>(x, Wg);

    cudaFuncSetAttribute(fused_moe, cudaFuncAttributeMaxDynamicSharedMemorySize, SMEM_TOT);
    fused_moe<<<dim3(B_ / 128, E_), 512, SMEM_TOT>>>(b1, b2, preds_out);

    combine_kernel<<<B_ / 8, 256>>>(preds_out, combined);
    if (has_counts) write_counts_kernel<<<1, 32>>>(out + n_combined + n_preds);
}

// round 8
// speedup vs baseline: 5.1006x; 1.0233x over previous
#include <cuda_runtime.h>
#include <cuda_fp16.h>
#include <cstdint>
#include <math.h>

#define B_ 32768
#define F_ 512
#define H_ 256
#define C_ 100
#define E_ 8

// ---------------- device-global scratch (no allocs allowed) ----------------
__device__ __align__(128) __half g_xH[(size_t)B_ * F_];           // 32 MB fp16
__device__ __align__(128) __half g_w1tH[(size_t)E_ * H_ * F_];    // [e][h][f] 2 MB
__device__ __align__(128) __half g_w2tH[(size_t)E_ * 128 * H_];   // [e][c pad128][h] 0.5 MB
__device__ float g_preds[(size_t)E_ * B_ * C_];
__device__ int   g_top2[B_];
__device__ int   g_counts[E_];

// ---------------- helpers ----------------
__device__ __forceinline__ uint32_t s2u(const void* p) {
    uint32_t a;
    asm("{ .reg .u64 t; cvta.to.shared.u64 t, %1; cvt.u32.u64 %0, t; }" : "=r"(a) : "l"(p));
    return a;
}
__device__ __forceinline__ uint32_t packh2(float f0, float f1) {
    __half h0 = __float2half_rn(f0), h1 = __float2half_rn(f1);
    return (uint32_t)__half_as_ushort(h0) | ((uint32_t)__half_as_ushort(h1) << 16);
}
__device__ __forceinline__ void ldm4(uint32_t* r, uint32_t a) {
    asm volatile("ldmatrix.sync.aligned.m8n8.x4.shared.b16 {%0,%1,%2,%3}, [%4];"
                 : "=r"(r[0]), "=r"(r[1]), "=r"(r[2]), "=r"(r[3]) : "r"(a));
}
__device__ __forceinline__ void mma16816(float* c, const uint32_t* a, const uint32_t* b) {
    asm volatile("mma.sync.aligned.m16n8k16.row.col.f32.f16.f16.f32 "
                 "{%0,%1,%2,%3}, {%4,%5,%6,%7}, {%8,%9}, {%0,%1,%2,%3};"
                 : "+f"(c[0]), "+f"(c[1]), "+f"(c[2]), "+f"(c[3])
                 : "r"(a[0]), "r"(a[1]), "r"(a[2]), "r"(a[3]), "r"(b[0]), "r"(b[1]));
}
__device__ __forceinline__ void cpa(uint32_t dst, const void* src) {
    asm volatile("cp.async.cg.shared.global [%0], [%1], 16;" :: "r"(dst), "l"(src));
}

// ---------------- merged prep kernel (fp32 -> fp16) ----------------
__global__ __launch_bounds__(256) void prep_all(const float* __restrict__ x,
                                                const float* __restrict__ W1,
                                                const float* __restrict__ W2) {
    int bid = blockIdx.x;
    if (bid < 8192) {
        size_t gid = (size_t)bid * 256 + threadIdx.x;
        const float4* s = (const float4*)(x + gid * 8);
        float4 f0 = s[0], f1 = s[1];
        uint4 hi;
        hi.x = packh2(f0.x, f0.y); hi.y = packh2(f0.z, f0.w);
        hi.z = packh2(f1.x, f1.y); hi.w = packh2(f1.z, f1.w);
        *(uint4*)(g_xH + gid * 8) = hi;
    } else if (bid < 8704) {
        int gid = (bid - 8192) * 256 + threadIdx.x;           // 8*256*64
        int e = gid >> 14, h = (gid >> 6) & 255, f8 = gid & 63;
        float f[8];
#pragma unroll
        for (int j = 0; j < 8; j++) f[j] = W1[((size_t)e * F_ + f8 * 8 + j) * H_ + h];
        uint4 hi;
        hi.x = packh2(f[0], f[1]); hi.y = packh2(f[2], f[3]);
        hi.z = packh2(f[4], f[5]); hi.w = packh2(f[6], f[7]);
        *(uint4*)(g_w1tH + ((size_t)e * H_ + h) * F_ + f8 * 8) = hi;
    } else {
        int gid = (bid - 8704) * 256 + threadIdx.x;           // 8*128*32
        int e = gid >> 12, c = (gid >> 5) & 127, h8 = gid & 31;
        float f[8];
#pragma unroll
        for (int j = 0; j < 8; j++)
            f[j] = (c < C_) ? W2[((size_t)e * H_ + h8 * 8 + j) * C_ + c] : 0.f;
        uint4 hi;
        hi.x = packh2(f[0], f[1]); hi.y = packh2(f[2], f[3]);
        hi.z = packh2(f[4], f[5]); hi.w = packh2(f[6], f[7]);
        *(uint4*)(g_w2tH + ((size_t)e * 128 + c) * H_ + h8 * 8) = hi;
    }
}

// ---------------- fused expert kernel ----------------
// GEMM1: h[128,256] = relu(x@W1^T + b1), 3-stage cp.async pipeline, 1 sync/stage.
// GEMM2: preds = h@W2^T + b2; whole W2 (64KB) loaded once, mainloop sync-free.
#define A1SZ 10240                 // A stage: 128 x 80B
#define STG1 30720                 // one GEMM1 stage: A + B(256x80B)
#define HSTR 528                   // row stride bytes (conflict-free for ldmatrix)
#define HHI  92160                 // h tile base (after 3 stages)
#define SMEM_TOT 159744            // 92160 staging(+W2 reuse) + 128*528 h

__global__ void __launch_bounds__(512, 1)
fused_moe(const float* __restrict__ b1g, const float* __restrict__ b2g,
          float* __restrict__ preds_arg) {
    extern __shared__ __align__(128) unsigned char sm[];
    const uint32_t sb = s2u(sm);
    const int tid = threadIdx.x;
    const int m0 = blockIdx.x * 128, e = blockIdx.y;
    float* preds = preds_arg ? preds_arg : g_preds;

    const __half* Asrc = g_xH + (size_t)m0 * F_;
    const __half* Bsrc = g_w1tH + (size_t)e * H_ * F_;
    const __half* Wsrc = g_w2tH + (size_t)e * 128 * H_;

    const int l = tid & 31, warp = tid >> 5, wr = warp & 3, wc = warp >> 2;

    auto load1 = [&](int buf, int k0) {
        {   // A: 128 rows x 32k
            int r = tid >> 2, kc = (tid & 3) * 8;
            cpa(sb + buf * STG1 + r * 80 + kc * 2, Asrc + (size_t)r * F_ + k0 + kc);
        }
#pragma unroll
        for (int j = 0; j < 2; j++) {   // B: 256 rows x 32k
            int idx = tid + j * 512;
            int r = idx >> 2, kc = (idx & 3) * 8;
            cpa(sb + buf * STG1 + A1SZ + r * 80 + kc * 2, Bsrc + (size_t)r * F_ + k0 + kc);
        }
        asm volatile("cp.async.commit_group;" ::: "memory");
    };

    // ---------------- GEMM1: 3-stage pipeline ----------------
    const uint32_t aOff = (uint32_t)(wr * 32 + (l & 15)) * 80 + (l >> 4) * 16;
    const uint32_t bOff = (uint32_t)(wc * 64 + ((l >> 4) << 3) + (l & 7)) * 80 + ((l >> 3) & 1) * 16;

    float acc[2][8][4];
#pragma unroll
    for (int i = 0; i < 2; i++)
#pragma unroll
        for (int j = 0; j < 8; j++)
#pragma unroll
            for (int q = 0; q < 4; q++) acc[i][j][q] = 0.f;

    load1(0, 0);
    load1(1, 32);
    const int NS1 = F_ / 32;   // 16
    int bufc = 0;              // compute buffer index (cycles 0,1,2)
    for (int s = 0; s < NS1; s++) {
        if (s + 1 < NS1) {
            asm volatile("cp.async.wait_group 1;" ::: "memory");
        } else {
            asm volatile("cp.async.wait_group 0;" ::: "memory");
        }
        __syncthreads();
        if (s + 2 < NS1) {
            int bl = bufc + 2; if (bl >= 3) bl -= 3;
            load1(bl, (s + 2) * 32);
        }
        const uint32_t base = sb + bufc * STG1;
#pragma unroll
        for (int h = 0; h < 2; h++) {
            uint32_t a4[2][4];
            ldm4(a4[0], base + aOff + h * 32);
            ldm4(a4[1], base + aOff + 16 * 80 + h * 32);
#pragma unroll
            for (int ni = 0; ni < 4; ni++) {
                uint32_t b4[4];
                ldm4(b4, base + A1SZ + bOff + ni * 16 * 80 + h * 32);
#pragma unroll
                for (int mi = 0; mi < 2; mi++)
#pragma unroll
                    for (int sj = 0; sj < 2; sj++)
                        mma16816(acc[mi][ni * 2 + sj], a4[mi], b4 + 2 * sj);
            }
        }
        if (++bufc == 3) bufc = 0;
    }

    // all staging reads done across the CTA before W2 overwrites staging
    __syncthreads();
    {   // load whole W2 [128 rows c][256 k] into staging region, stride 528
#pragma unroll
        for (int j = 0; j < 8; j++) {
            int idx = tid + j * 512;             // 4096 16B-chunks
            int r = idx >> 5, kc16 = idx & 31;
            cpa(sb + r * HSTR + kc16 * 16, Wsrc + (size_t)r * H_ + kc16 * 8);
        }
        asm volatile("cp.async.commit_group;" ::: "memory");
    }

    // ---------------- epilogue 1: relu(+b1) -> fp16 h in SMEM (overlaps W2 load) ----
    {
        const float* bs1 = b1g + e * H_;
#pragma unroll
        for (int mi = 0; mi < 2; mi++) {
            int rB = wr * 32 + mi * 16 + (l >> 2);
#pragma unroll
            for (int ni = 0; ni < 8; ni++) {
                int n = wc * 64 + ni * 8 + (l & 3) * 2;
#pragma unroll
                for (int hf = 0; hf < 2; hf++) {
                    int r = rB + hf * 8;
                    float v0 = fmaxf(acc[mi][ni][hf * 2 + 0] + bs1[n], 0.f);
                    float v1 = fmaxf(acc[mi][ni][hf * 2 + 1] + bs1[n + 1], 0.f);
                    *(uint32_t*)(sm + HHI + r * HSTR + n * 2) = packh2(v0, v1);
                }
            }
        }
    }
    asm volatile("cp.async.wait_group 0;" ::: "memory");
    __syncthreads();   // publishes h and W2

    // ---------------- GEMM2: h @ W2^T, sync-free mainloop ----------------
    const uint32_t a2Off = (uint32_t)(wr * 32 + (l & 15)) * HSTR + (l >> 4) * 16;
    const uint32_t b2Off = (uint32_t)(wc * 32 + ((l >> 4) << 3) + (l & 7)) * HSTR + ((l >> 3) & 1) * 16;

    float acc2[2][4][4];
#pragma unroll
    for (int i = 0; i < 2; i++)
#pragma unroll
        for (int j = 0; j < 4; j++)
#pragma unroll
            for (int q = 0; q < 4; q++) acc2[i][j][q] = 0.f;

#pragma unroll
    for (int s = 0; s < H_ / 32; s++) {
#pragma unroll
        for (int h = 0; h < 2; h++) {
            uint32_t ah[2][4];
            ldm4(ah[0], sb + HHI + a2Off + s * 64 + h * 32);
            ldm4(ah[1], sb + HHI + a2Off + 16 * HSTR + s * 64 + h * 32);
#pragma unroll
            for (int ni = 0; ni < 2; ni++) {
                uint32_t b4[4];
                ldm4(b4, sb + b2Off + ni * 16 * HSTR + s * 64 + h * 32);
#pragma unroll
                for (int mi = 0; mi < 2; mi++)
#pragma unroll
                    for (int sj = 0; sj < 2; sj++)
                        mma16816(acc2[mi][ni * 2 + sj], ah[mi], b4 + 2 * sj);
            }
        }
    }

    // ---------------- epilogue 2: + b2 -> preds ----------------
    {
        const float* bs2 = b2g + e * C_;
#pragma unroll
        for (int mi = 0; mi < 2; mi++) {
            int mB = m0 + wr * 32 + mi * 16 + (l >> 2);
#pragma unroll
            for (int ni = 0; ni < 4; ni++) {
                int n = wc * 32 + ni * 8 + (l & 3) * 2;
#pragma unroll
                for (int hf = 0; hf < 2; hf++) {
                    int m = mB + hf * 8;
                    size_t o = ((size_t)e * B_ + m) * C_;
                    if (n < C_)     preds[o + n]     = acc2[mi][ni][hf * 2 + 0] + bs2[n];
                    if (n + 1 < C_) preds[o + n + 1] = acc2[mi][ni][hf * 2 + 1] + bs2[n + 1];
                }
            }
        }
    }
}

// ---------------- gating ----------------
__global__ __launch_bounds__(256) void gate_kernel(const float* __restrict__ x,
                                                   const float* __restrict__ Wg) {
    __shared__ float wgs[F_ * 9];
    __shared__ int cnt[E_];
    const int tid = threadIdx.x;
    if (tid < E_) cnt[tid] = 0;
    for (int i = tid; i < F_ * E_; i += 256) {
        int f = i >> 3, e = i & 7;
        wgs[f * 9 + e] = Wg[i];
    }
    __syncthreads();
    const int warp = tid >> 5, lane = tid & 31;
    const int row = blockIdx.x * 8 + warp;
    const float* xr = x + (size_t)row * F_;
    float acc[E_];
#pragma unroll
    for (int e = 0; e < E_; e++) acc[e] = 0.f;
#pragma unroll
    for (int i = 0; i < F_ / 32; i++) {
        int f = i * 32 + lane;
        float xv = xr[f];
#pragma unroll
        for (int e = 0; e < E_; e++) acc[e] += xv * wgs[f * 9 + e];
    }
#pragma unroll
    for (int off = 16; off; off >>= 1)
#pragma unroll
        for (int e = 0; e < E_; e++) acc[e] += __shfl_xor_sync(0xffffffffu, acc[e], off);
    if (lane == 0) {
        int i1 = 0;
#pragma unroll
        for (int e = 1; e < E_; e++) if (acc[e] > acc[i1]) i1 = e;
        int i2 = (i1 == 0) ? 1 : 0;
#pragma unroll
        for (int e = 0; e < E_; e++) if (e != i1 && acc[e] > acc[i2]) i2 = e;
        g_top2[row] = i1 | (i2 << 8);
        atomicAdd(&cnt[i1], 1);
        atomicAdd(&cnt[i2], 1);
    }
    __syncthreads();
    if (tid < E_ && cnt[tid]) atomicAdd(&g_counts[tid], cnt[tid]);
}

// ---------------- combine ----------------
__global__ __launch_bounds__(256)
void combine_kernel(const float* __restrict__ preds_arg, float* __restrict__ combined) {
    const float* preds = preds_arg ? preds_arg : g_preds;
    const int warp = threadIdx.x >> 5, lane = threadIdx.x & 31;
    const int row = blockIdx.x * 8 + warp;
    const int packed = g_top2[row];
    const int e1 = packed & 0xFF, e2 = (packed >> 8) & 0xFF;
    const float* p1 = preds + ((size_t)e1 * B_ + row) * C_;
    const float* p2 = preds + ((size_t)e2 * B_ + row) * C_;
    float v1[4], v2[4];
#pragma unroll
    for (int i = 0; i < 4; i++) {
        int c = lane + i * 32;
        bool ok = c < C_;
        v1[i] = ok ? p1[c] : -3.4e38f;
        v2[i] = ok ? p2[c] : -3.4e38f;
    }
    float m1 = fmaxf(fmaxf(v1[0], v1[1]), fmaxf(v1[2], v1[3]));
    float m2 = fmaxf(fmaxf(v2[0], v2[1]), fmaxf(v2[2], v2[3]));
#pragma unroll
    for (int off = 16; off; off >>= 1) {
        m1 = fmaxf(m1, __shfl_xor_sync(0xffffffffu, m1, off));
        m2 = fmaxf(m2, __shfl_xor_sync(0xffffffffu, m2, off));
    }
    float s1 = 0.f, s2 = 0.f;
#pragma unroll
    for (int i = 0; i < 4; i++) {
        int c = lane + i * 32;
        v1[i] = (c < C_) ? expf(v1[i] - m1) : 0.f;
        v2[i] = (c < C_) ? expf(v2[i] - m2) : 0.f;
        s1 += v1[i]; s2 += v2[i];
    }
#pragma unroll
    for (int off = 16; off; off >>= 1) {
        s1 += __shfl_xor_sync(0xffffffffu, s1, off);
        s2 += __shfl_xor_sync(0xffffffffu, s2, off);
    }
    const float r1 = 0.5f / s1, r2 = 0.5f / s2;
    float* outr = combined + (size_t)row * C_;
#pragma unroll
    for (int i = 0; i < 4; i++) {
        int c = lane + i * 32;
        if (c < C_) outr[c] = v1[i] * r1 + v2[i] * r2;
    }
}

__global__ void zero_counts_kernel() { if (threadIdx.x < E_) g_counts[threadIdx.x] = 0; }
__global__ void write_counts_kernel(float* __restrict__ dst) {
    if (threadIdx.x < E_) dst[threadIdx.x] = (float)g_counts[threadIdx.x];
}

// ---------------------------------------------------------------------------
extern "C" void kernel_launch(void* const* d_in, const int* in_sizes, int n_in,
                              void* d_out, int out_size) {
    const float* x  = (const float*)d_in[0];
    const float* W1 = (const float*)d_in[1];
    const float* b1 = (const float*)d_in[2];
    const float* W2 = (const float*)d_in[3];
    const float* b2 = (const float*)d_in[4];
    const float* Wg = (const float*)d_in[5];
    float* out = (float*)d_out;

    const size_t n_combined = (size_t)B_ * C_;
    const size_t n_preds    = (size_t)E_ * B_ * C_;
    const bool has_preds  = (size_t)out_size >= n_combined + n_preds;
    const bool has_counts = (size_t)out_size >= n_combined + n_preds + E_;
    float* combined  = out;
    float* preds_out = has_preds ? out + n_combined : nullptr;

    zero_counts_kernel<<<1, 32>>>();
    prep_all<<<8832, 256>>>(x, W1, W2);
    gate_kernel<<<B_ / 8, 256>>>(x, Wg);

    cudaFuncSetAttribute(fused_moe, cudaFuncAttributeMaxDynamicSharedMemorySize, SMEM_TOT);
    fused_moe<<<dim3(B_ / 128, E_), 512, SMEM_TOT>>>(b1, b2, preds_out);

    combine_kernel<<<B_ / 8, 256>>>(preds_out, combined);
    if (has_counts) write_counts_kernel<<<1, 32>>>(out + n_combined + n_preds);
}

// round 10
// speedup vs baseline: 5.4357x; 1.0657x over previous
#include <cuda_runtime.h>
#include <cuda_fp16.h>
#include <cstdint>
#include <math.h>

#define B_ 32768
#define F_ 512
#define H_ 256
#define C_ 100
#define E_ 8

// ---------------- device-global scratch (no allocs allowed) ----------------
__device__ __align__(128) __half g_xH[(size_t)B_ * F_];           // 32 MB fp16
__device__ __align__(128) __half g_w1tH[(size_t)E_ * H_ * F_];    // [e][h][f] 2 MB
__device__ __align__(128) __half g_w2tH[(size_t)E_ * 128 * H_];   // [e][c pad128][h] 0.5 MB
__device__ float g_preds[(size_t)E_ * B_ * C_];
__device__ int   g_top2[B_];
__device__ int   g_counts[E_];

// ---------------- helpers ----------------
__device__ __forceinline__ uint32_t s2u(const void* p) {
    uint32_t a;
    asm("{ .reg .u64 t; cvta.to.shared.u64 t, %1; cvt.u32.u64 %0, t; }" : "=r"(a) : "l"(p));
    return a;
}
__device__ __forceinline__ uint32_t packh2(float f0, float f1) {
    __half h0 = __float2half_rn(f0), h1 = __float2half_rn(f1);
    return (uint32_t)__half_as_ushort(h0) | ((uint32_t)__half_as_ushort(h1) << 16);
}
__device__ __forceinline__ void ldm4(uint32_t* r, uint32_t a) {
    asm volatile("ldmatrix.sync.aligned.m8n8.x4.shared.b16 {%0,%1,%2,%3}, [%4];"
                 : "=r"(r[0]), "=r"(r[1]), "=r"(r[2]), "=r"(r[3]) : "r"(a));
}
__device__ __forceinline__ void mma16816(float* c, const uint32_t* a, const uint32_t* b) {
    asm volatile("mma.sync.aligned.m16n8k16.row.col.f32.f16.f16.f32 "
                 "{%0,%1,%2,%3}, {%4,%5,%6,%7}, {%8,%9}, {%0,%1,%2,%3};"
                 : "+f"(c[0]), "+f"(c[1]), "+f"(c[2]), "+f"(c[3])
                 : "r"(a[0]), "r"(a[1]), "r"(a[2]), "r"(a[3]), "r"(b[0]), "r"(b[1]));
}
__device__ __forceinline__ void cpa(uint32_t dst, const void* src) {
    asm volatile("cp.async.cg.shared.global [%0], [%1], 16;" :: "r"(dst), "l"(src));
}

// ---------------- merged prep kernel (fp32 -> fp16) ----------------
__global__ __launch_bounds__(256) void prep_all(const float* __restrict__ x,
                                                const float* __restrict__ W1,
                                                const float* __restrict__ W2) {
    int bid = blockIdx.x;
    if (bid < 8192) {
        size_t gid = (size_t)bid * 256 + threadIdx.x;
        const float4* s = (const float4*)(x + gid * 8);
        float4 f0 = s[0], f1 = s[1];
        uint4 hi;
        hi.x = packh2(f0.x, f0.y); hi.y = packh2(f0.z, f0.w);
        hi.z = packh2(f1.x, f1.y); hi.w = packh2(f1.z, f1.w);
        *(uint4*)(g_xH + gid * 8) = hi;
    } else if (bid < 8704) {
        int gid = (bid - 8192) * 256 + threadIdx.x;           // 8*256*64
        int e = gid >> 14, h = (gid >> 6) & 255, f8 = gid & 63;
        float f[8];
#pragma unroll
        for (int j = 0; j < 8; j++) f[j] = W1[((size_t)e * F_ + f8 * 8 + j) * H_ + h];
        uint4 hi;
        hi.x = packh2(f[0], f[1]); hi.y = packh2(f[2], f[3]);
        hi.z = packh2(f[4], f[5]); hi.w = packh2(f[6], f[7]);
        *(uint4*)(g_w1tH + ((size_t)e * H_ + h) * F_ + f8 * 8) = hi;
    } else {
        int gid = (bid - 8704) * 256 + threadIdx.x;           // 8*128*32
        int e = gid >> 12, c = (gid >> 5) & 127, h8 = gid & 31;
        float f[8];
#pragma unroll
        for (int j = 0; j < 8; j++)
            f[j] = (c < C_) ? W2[((size_t)e * H_ + h8 * 8 + j) * C_ + c] : 0.f;
        uint4 hi;
        hi.x = packh2(f[0], f[1]); hi.y = packh2(f[2], f[3]);
        hi.z = packh2(f[4], f[5]); hi.w = packh2(f[6], f[7]);
        *(uint4*)(g_w2tH + ((size_t)e * 128 + c) * H_ + h8 * 8) = hi;
    }
}

// ---------------- fused expert kernel (M=64 CTA, 2 CTAs/SM) ----------------
// GEMM1: h[64,256] = relu(x@W1^T + b1), 3-stage cp.async pipeline.
// GEMM2: preds = h@W2^T + b2; whole W2 (128 rows x 512B, stride 528) loaded once;
//        sync-free mainloop.
#define A1SZ 5120                  // A stage: 64 x 80B
#define STG1 25600                 // one GEMM1 stage: A + B(256x80B)
#define HSTR 528                   // row stride bytes (512B data + 16B pad, conflict-free)
#define HHI  76800                 // h tile base (after 3 stages; W2 reuses staging)
#define SMEM_TOT 110592            // 76800 staging(+W2 reuse 67584) + 64*528 h

__global__ void __launch_bounds__(256, 2)
fused_moe(const float* __restrict__ b1g, const float* __restrict__ b2g,
          float* __restrict__ preds_arg) {
    extern __shared__ __align__(128) unsigned char sm[];
    const uint32_t sb = s2u(sm);
    const int tid = threadIdx.x;
    const int m0 = blockIdx.x * 64, e = blockIdx.y;
    float* preds = preds_arg ? preds_arg : g_preds;

    const __half* Asrc = g_xH + (size_t)m0 * F_;
    const __half* Bsrc = g_w1tH + (size_t)e * H_ * F_;
    const __half* Wsrc = g_w2tH + (size_t)e * 128 * H_;

    const int l = tid & 31, warp = tid >> 5, wr = warp & 1, wc = warp >> 1;

    auto load1 = [&](int buf, int k0) {
        {   // A: 64 rows x 32k -> 256 chunks of 16B
            int r = tid >> 2, kc = (tid & 3) * 8;
            cpa(sb + buf * STG1 + r * 80 + kc * 2, Asrc + (size_t)r * F_ + k0 + kc);
        }
#pragma unroll
        for (int j = 0; j < 4; j++) {   // B: 256 rows x 32k -> 1024 chunks
            int idx = tid + j * 256;
            int r = idx >> 2, kc = (idx & 3) * 8;
            cpa(sb + buf * STG1 + A1SZ + r * 80 + kc * 2, Bsrc + (size_t)r * F_ + k0 + kc);
        }
        asm volatile("cp.async.commit_group;" ::: "memory");
    };

    // ---------------- GEMM1: 3-stage pipeline, warp tile m32n64 ----------------
    const uint32_t aOff = (uint32_t)(wr * 32 + (l & 15)) * 80 + (l >> 4) * 16;
    const uint32_t bOff = (uint32_t)(wc * 64 + ((l >> 4) << 3) + (l & 7)) * 80 + ((l >> 3) & 1) * 16;

    float acc[2][8][4];
#pragma unroll
    for (int i = 0; i < 2; i++)
#pragma unroll
        for (int j = 0; j < 8; j++)
#pragma unroll
            for (int q = 0; q < 4; q++) acc[i][j][q] = 0.f;

    load1(0, 0);
    load1(1, 32);
    const int NS1 = F_ / 32;   // 16
    int bufc = 0;
    for (int s = 0; s < NS1; s++) {
        if (s + 1 < NS1) {
            asm volatile("cp.async.wait_group 1;" ::: "memory");
        } else {
            asm volatile("cp.async.wait_group 0;" ::: "memory");
        }
        __syncthreads();
        if (s + 2 < NS1) {
            int bl = bufc + 2; if (bl >= 3) bl -= 3;
            load1(bl, (s + 2) * 32);
        }
        const uint32_t base = sb + bufc * STG1;
#pragma unroll
        for (int h = 0; h < 2; h++) {
            uint32_t a4[2][4];
            ldm4(a4[0], base + aOff + h * 32);
            ldm4(a4[1], base + aOff + 16 * 80 + h * 32);
#pragma unroll
            for (int ni = 0; ni < 4; ni++) {
                uint32_t b4[4];
                ldm4(b4, base + A1SZ + bOff + ni * 16 * 80 + h * 32);
#pragma unroll
                for (int mi = 0; mi < 2; mi++)
#pragma unroll
                    for (int sj = 0; sj < 2; sj++)
                        mma16816(acc[mi][ni * 2 + sj], a4[mi], b4 + 2 * sj);
            }
        }
        if (++bufc == 3) bufc = 0;
    }

    // staging reads done before W2 overwrites staging
    __syncthreads();
    {   // load whole W2 [128 rows c][256 k = 512B] into staging region, stride 528
#pragma unroll
        for (int j = 0; j < 16; j++) {
            int idx = tid + j * 256;             // 4096 16B-chunks
            int r = idx >> 5, kc16 = idx & 31;
            cpa(sb + r * HSTR + kc16 * 16, Wsrc + (size_t)r * H_ + kc16 * 8);
        }
        asm volatile("cp.async.commit_group;" ::: "memory");
    }

    // ---------------- epilogue 1: relu(+b1) -> fp16 h in SMEM (overlaps W2 load) ----
    {
        const float* bs1 = b1g + e * H_;
#pragma unroll
        for (int mi = 0; mi < 2; mi++) {
            int rB = wr * 32 + mi * 16 + (l >> 2);
#pragma unroll
            for (int ni = 0; ni < 8; ni++) {
                int n = wc * 64 + ni * 8 + (l & 3) * 2;
#pragma unroll
                for (int hf = 0; hf < 2; hf++) {
                    int r = rB + hf * 8;
                    float v0 = fmaxf(acc[mi][ni][hf * 2 + 0] + bs1[n], 0.f);
                    float v1 = fmaxf(acc[mi][ni][hf * 2 + 1] + bs1[n + 1], 0.f);
                    *(uint32_t*)(sm + HHI + r * HSTR + n * 2) = packh2(v0, v1);
                }
            }
        }
    }
    asm volatile("cp.async.wait_group 0;" ::: "memory");
    __syncthreads();   // publishes h and W2

    // ---------------- GEMM2: h @ W2^T, warp tile m32n32, sync-free ----------------
    const uint32_t a2Off = (uint32_t)(wr * 32 + (l & 15)) * HSTR + (l >> 4) * 16;
    const uint32_t b2Off = (uint32_t)(wc * 32 + ((l >> 4) << 3) + (l & 7)) * HSTR + ((l >> 3) & 1) * 16;

    float acc2[2][4][4];
#pragma unroll
    for (int i = 0; i < 2; i++)
#pragma unroll
        for (int j = 0; j < 4; j++)
#pragma unroll
            for (int q = 0; q < 4; q++) acc2[i][j][q] = 0.f;

#pragma unroll
    for (int s = 0; s < H_ / 32; s++) {
#pragma unroll
        for (int h = 0; h < 2; h++) {
            uint32_t ah[2][4];
            ldm4(ah[0], sb + HHI + a2Off + s * 64 + h * 32);
            ldm4(ah[1], sb + HHI + a2Off + 16 * HSTR + s * 64 + h * 32);
#pragma unroll
            for (int ni = 0; ni < 2; ni++) {
                uint32_t b4[4];
                ldm4(b4, sb + b2Off + ni * 16 * HSTR + s * 64 + h * 32);
#pragma unroll
                for (int mi = 0; mi < 2; mi++)
#pragma unroll
                    for (int sj = 0; sj < 2; sj++)
                        mma16816(acc2[mi][ni * 2 + sj], ah[mi], b4 + 2 * sj);
            }
        }
    }

    // ---------------- epilogue 2: + b2 -> preds ----------------
    {
        const float* bs2 = b2g + e * C_;
#pragma unroll
        for (int mi = 0; mi < 2; mi++) {
            int mB = m0 + wr * 32 + mi * 16 + (l >> 2);
#pragma unroll
            for (int ni = 0; ni < 4; ni++) {
                int n = wc * 32 + ni * 8 + (l & 3) * 2;
#pragma unroll
                for (int hf = 0; hf < 2; hf++) {
                    int m = mB + hf * 8;
                    size_t o = ((size_t)e * B_ + m) * C_;
                    if (n < C_)     preds[o + n]     = acc2[mi][ni][hf * 2 + 0] + bs2[n];
                    if (n + 1 < C_) preds[o + n + 1] = acc2[mi][ni][hf * 2 + 1] + bs2[n + 1];
                }
            }
        }
    }
}

// ---------------- gating ----------------
__global__ __launch_bounds__(256) void gate_kernel(const float* __restrict__ x,
                                                   const float* __restrict__ Wg) {
    __shared__ float wgs[F_ * 9];
    __shared__ int cnt[E_];
    const int tid = threadIdx.x;
    if (tid < E_) cnt[tid] = 0;
    for (int i = tid; i < F_ * E_; i += 256) {
        int f = i >> 3, e = i & 7;
        wgs[f * 9 + e] = Wg[i];
    }
    __syncthreads();
    const int warp = tid >> 5, lane = tid & 31;
    const int row = blockIdx.x * 8 + warp;
    const float* xr = x + (size_t)row * F_;
    float acc[E_];
#pragma unroll
    for (int e = 0; e < E_; e++) acc[e] = 0.f;
#pragma unroll
    for (int i = 0; i < F_ / 32; i++) {
        int f = i * 32 + lane;
        float xv = xr[f];
#pragma unroll
        for (int e = 0; e < E_; e++) acc[e] += xv * wgs[f * 9 + e];
    }
#pragma unroll
    for (int off = 16; off; off >>= 1)
#pragma unroll
        for (int e = 0; e < E_; e++) acc[e] += __shfl_xor_sync(0xffffffffu, acc[e], off);
    if (lane == 0) {
        int i1 = 0;
#pragma unroll
        for (int e = 1; e < E_; e++) if (acc[e] > acc[i1]) i1 = e;
        int i2 = (i1 == 0) ? 1 : 0;
#pragma unroll
        for (int e = 0; e < E_; e++) if (e != i1 && acc[e] > acc[i2]) i2 = e;
        g_top2[row] = i1 | (i2 << 8);
        atomicAdd(&cnt[i1], 1);
        atomicAdd(&cnt[i2], 1);
    }
    __syncthreads();
    if (tid < E_ && cnt[tid]) atomicAdd(&g_counts[tid], cnt[tid]);
}

// ---------------- combine ----------------
__global__ __launch_bounds__(256)
void combine_kernel(const float* __restrict__ preds_arg, float* __restrict__ combined) {
    const float* preds = preds_arg ? preds_arg : g_preds;
    const int warp = threadIdx.x >> 5, lane = threadIdx.x & 31;
    const int row = blockIdx.x * 8 + warp;
    const int packed = g_top2[row];
    const int e1 = packed & 0xFF, e2 = (packed >> 8) & 0xFF;
    const float* p1 = preds + ((size_t)e1 * B_ + row) * C_;
    const float* p2 = preds + ((size_t)e2 * B_ + row) * C_;
    float v1[4], v2[4];
#pragma unroll
    for (int i = 0; i < 4; i++) {
        int c = lane + i * 32;
        bool ok = c < C_;
        v1[i] = ok ? p1[c] : -3.4e38f;
        v2[i] = ok ? p2[c] : -3.4e38f;
    }
    float m1 = fmaxf(fmaxf(v1[0], v1[1]), fmaxf(v1[2], v1[3]));
    float m2 = fmaxf(fmaxf(v2[0], v2[1]), fmaxf(v2[2], v2[3]));
#pragma unroll
    for (int off = 16; off; off >>= 1) {
        m1 = fmaxf(m1, __shfl_xor_sync(0xffffffffu, m1, off));
        m2 = fmaxf(m2, __shfl_xor_sync(0xffffffffu, m2, off));
    }
    float s1 = 0.f, s2 = 0.f;
#pragma unroll
    for (int i = 0; i < 4; i++) {
        int c = lane + i * 32;
        v1[i] = (c < C_) ? expf(v1[i] - m1) : 0.f;
        v2[i] = (c < C_) ? expf(v2[i] - m2) : 0.f;
        s1 += v1[i]; s2 += v2[i];
    }
#pragma unroll
    for (int off = 16; off; off >>= 1) {
        s1 += __shfl_xor_sync(0xffffffffu, s1, off);
        s2 += __shfl_xor_sync(0xffffffffu, s2, off);
    }
    const float r1 = 0.5f / s1, r2 = 0.5f / s2;
    float* outr = combined + (size_t)row * C_;
#pragma unroll
    for (int i = 0; i < 4; i++) {
        int c = lane + i * 32;
        if (c < C_) outr[c] = v1[i] * r1 + v2[i] * r2;
    }
}

__global__ void zero_counts_kernel() { if (threadIdx.x < E_) g_counts[threadIdx.x] = 0; }
__global__ void write_counts_kernel(float* __restrict__ dst) {
    if (threadIdx.x < E_) dst[threadIdx.x] = (float)g_counts[threadIdx.x];
}

// ---------------------------------------------------------------------------
extern "C" void kernel_launch(void* const* d_in, const int* in_sizes, int n_in,
                              void* d_out, int out_size) {
    const float* x  = (const float*)d_in[0];
    const float* W1 = (const float*)d_in[1];
    const float* b1 = (const float*)d_in[2];
    const float* W2 = (const float*)d_in[3];
    const float* b2 = (const float*)d_in[4];
    const float* Wg = (const float*)d_in[5];
    float* out = (float*)d_out;

    const size_t n_combined = (size_t)B_ * C_;
    const size_t n_preds    = (size_t)E_ * B_ * C_;
    const bool has_preds  = (size_t)out_size >= n_combined + n_preds;
    const bool has_counts = (size_t)out_size >= n_combined + n_preds + E_;
    float* combined  = out;
    float* preds_out = has_preds ? out + n_combined : nullptr;

    zero_counts_kernel<<<1, 32>>>();
    prep_all<<<8832, 256>>>(x, W1, W2);
    gate_kernel<<<B_ / 8, 256>>>(x, Wg);

    cudaFuncSetAttribute(fused_moe, cudaFuncAttributeMaxDynamicSharedMemorySize, SMEM_TOT);
    fused_moe<<<dim3(B_ / 64, E_), 256, SMEM_TOT>>>(b1, b2, preds_out);

    combine_kernel<<<B_ / 8, 256>>>(preds_out, combined);
    if (has_counts) write_counts_kernel<<<1, 32>>>(out + n_combined + n_preds);
}